// round 1
// baseline (speedup 1.0000x reference)
#include <cuda_runtime.h>

#define TT   4
#define CCH  256
#define HH   48
#define WWD  48
#define PP   2304          // 48*48
#define R5   6400          // 256*25
#define R3   6912          // 256*27
#define OFFC 200           // 4*2*25

// ---------------- scratch (static device globals; no allocation) ----------------
__device__ float g_woff_t [R5 * 256];   // [r][o] zero-padded to 256 cols
__device__ float g_wdef_t [R5 * 256];
__device__ float g_wtemp_t[R3 * 256];
__device__ float g_off    [TT * OFFC * PP];   // [t][och][p]
__device__ float g_B      [TT * R3 * PP];     // reused: B5 -> BD -> B3 (255 MB)

// ---------------- weight transpose: src[O][R] -> dst[R][256] (pad 0) ----------------
__global__ void transpose_pad(const float* __restrict__ src, float* __restrict__ dst,
                              int O, int R) {
    int idx = blockIdx.x * 256 + threadIdx.x;  // grid = R blocks -> idx < R*256
    int r = idx >> 8;
    int o = idx & 255;
    dst[idx] = (o < O) ? src[o * R + r] : 0.0f;
}

// ---------------- im2col for 1x5x5 conv, pad 2 ----------------
__global__ void im2col5_k(const float* __restrict__ x, float* __restrict__ B) {
    int t = blockIdx.x, c = blockIdx.y;
    const float* xs = x + (c * TT + t) * PP;
    for (int k = 0; k < 25; k++) {
        int ky = k / 5 - 2, kx = k % 5 - 2;
        float* dst = B + (t * R5 + c * 25 + k) * PP;
        for (int p = threadIdx.x; p < PP; p += 256) {
            int y = p / WWD + ky, xx = p % WWD + kx;
            float v = (y >= 0 && y < HH && xx >= 0 && xx < WWD) ? xs[y * WWD + xx] : 0.0f;
            dst[p] = v;
        }
    }
}

// ---------------- im2col for 3x3x3 conv, pad 1 (incl. temporal) ----------------
__global__ void im2col3_k(const float* __restrict__ x, float* __restrict__ B) {
    int t = blockIdx.x, c = blockIdx.y;
    for (int q = 0; q < 27; q++) {
        int kt = q / 9 - 1, ky = (q / 3) % 3 - 1, kx = q % 3 - 1;
        int tt = t + kt;
        bool tval = (tt >= 0 && tt < TT);
        const float* xs = x + (c * TT + (tval ? tt : 0)) * PP;
        float* dst = B + (t * R3 + c * 27 + q) * PP;
        for (int p = threadIdx.x; p < PP; p += 256) {
            int y = p / WWD + ky, xx = p % WWD + kx;
            float v = (tval && y >= 0 && y < HH && xx >= 0 && xx < WWD)
                        ? xs[y * WWD + xx] : 0.0f;
            dst[p] = v;
        }
    }
}

// ---------------- bilinear sampling into B: r = c*25 + k ----------------
__global__ void sample_k(const float* __restrict__ x, const float* __restrict__ off,
                         float* __restrict__ B) {
    int t = blockIdx.x, dg = blockIdx.y, k = blockIdx.z;
    int ky = k / 5 - 2, kx = k % 5 - 2;
    const float* offy = off + (t * OFFC + (dg * 25 + k) * 2) * PP;
    const float* offx = offy + PP;
    const float* xb = x + ((dg * 64) * TT + t) * PP;   // base channel of group
    float* dstb = B + (t * R5 + (dg * 64) * 25 + k) * PP;

    for (int p = threadIdx.x; p < PP; p += 256) {
        float sy = (float)(p / WWD + ky) + offy[p];
        float sx = (float)(p % WWD + kx) + offx[p];
        float fy = floorf(sy), fx = floorf(sx);
        int y0 = (int)fy, x0 = (int)fx;
        float wy = sy - fy, wx = sx - fx;
        int y1 = y0 + 1, x1 = x0 + 1;
        float vy0 = (y0 >= 0 && y0 < HH) ? 1.0f : 0.0f;
        float vy1 = (y1 >= 0 && y1 < HH) ? 1.0f : 0.0f;
        float vx0 = (x0 >= 0 && x0 < WWD) ? 1.0f : 0.0f;
        float vx1 = (x1 >= 0 && x1 < WWD) ? 1.0f : 0.0f;
        int y0c = min(max(y0, 0), HH - 1), y1c = min(max(y1, 0), HH - 1);
        int x0c = min(max(x0, 0), WWD - 1), x1c = min(max(x1, 0), WWD - 1);
        float w00 = (1.0f - wy) * (1.0f - wx) * vy0 * vx0;
        float w01 = (1.0f - wy) * wx          * vy0 * vx1;
        float w10 = wy          * (1.0f - wx) * vy1 * vx0;
        float w11 = wy          * wx          * vy1 * vx1;
        int i00 = y0c * WWD + x0c, i01 = y0c * WWD + x1c;
        int i10 = y1c * WWD + x0c, i11 = y1c * WWD + x1c;

        float* dst = dstb + p;
        #pragma unroll 4
        for (int c = 0; c < 64; c++) {
            const float* xc = xb + c * (TT * PP);
            float v = w00 * xc[i00] + w01 * xc[i01] + w10 * xc[i10] + w11 * xc[i11];
            dst[c * 25 * PP] = v;
        }
    }
}

// ---------------- shared fp32 GEMM: out[o][t][p] (+)= sum_r A[r][o] * B[t][r][p] ----------------
// Tiles: O_TILE=128, P_TILE=64, CH=16. 256 threads, 8x4 register tile per thread.
__global__ __launch_bounds__(256) void gemm_k(
    const float* __restrict__ A,    // [R][256]  (zero padded cols)
    const float* __restrict__ Bm,   // [T][R][P]
    float* __restrict__ outp,
    int R, int O, int o_stride, int t_stride,
    const float* __restrict__ bias, int accumulate)
{
    __shared__ float As[16][128];
    __shared__ float Bs[16][64];
    int p0 = blockIdx.x * 64;
    int t  = blockIdx.y;
    int o0 = blockIdx.z * 128;
    int tid = threadIdx.x;
    int tx = tid & 15, ty = tid >> 4;
    const float* Bt = Bm + (size_t)t * R * PP;

    float acc[8][4];
    #pragma unroll
    for (int i = 0; i < 8; i++)
        #pragma unroll
        for (int j = 0; j < 4; j++) acc[i][j] = 0.0f;

    for (int r0 = 0; r0 < R; r0 += 16) {
        #pragma unroll
        for (int l = 0; l < 2; l++) {
            int lin = l * 256 + tid;
            int row = lin >> 5, col = (lin & 31) << 2;
            *(float4*)&As[row][col] = *(const float4*)&A[(r0 + row) * 256 + o0 + col];
        }
        {
            int row = tid >> 4, col = (tid & 15) << 2;
            *(float4*)&Bs[row][col] = *(const float4*)&Bt[(r0 + row) * PP + p0 + col];
        }
        __syncthreads();
        #pragma unroll
        for (int kk = 0; kk < 16; kk++) {
            float4 a0 = *(float4*)&As[kk][ty * 4];
            float4 a1 = *(float4*)&As[kk][64 + ty * 4];
            float4 b  = *(float4*)&Bs[kk][tx * 4];
            float av[8] = {a0.x, a0.y, a0.z, a0.w, a1.x, a1.y, a1.z, a1.w};
            float bv[4] = {b.x, b.y, b.z, b.w};
            #pragma unroll
            for (int i = 0; i < 8; i++)
                #pragma unroll
                for (int j = 0; j < 4; j++)
                    acc[i][j] += av[i] * bv[j];
        }
        __syncthreads();
    }

    #pragma unroll
    for (int i = 0; i < 8; i++) {
        int o = o0 + ((i < 4) ? (ty * 4 + i) : (64 + ty * 4 + (i - 4)));
        if (o < O) {
            float bval = (bias != nullptr) ? bias[o] : 0.0f;
            #pragma unroll
            for (int j = 0; j < 4; j++) {
                int p = p0 + tx * 4 + j;
                int oi = o * o_stride + t * t_stride + p;
                float v = acc[i][j] + bval;
                if (accumulate) v += outp[oi];
                outp[oi] = v;
            }
        }
    }
}

// ---------------- launch ----------------
extern "C" void kernel_launch(void* const* d_in, const int* in_sizes, int n_in,
                              void* d_out, int out_size) {
    (void)in_sizes; (void)n_in; (void)out_size;
    const float* x      = (const float*)d_in[0];
    const float* w_off  = (const float*)d_in[1];
    const float* w_def  = (const float*)d_in[2];
    const float* w_temp = (const float*)d_in[3];
    const float* b_temp = (const float*)d_in[4];
    float* out = (float*)d_out;

    float *woff_t, *wdef_t, *wtemp_t, *offp, *Bp;
    cudaGetSymbolAddress((void**)&woff_t,  g_woff_t);
    cudaGetSymbolAddress((void**)&wdef_t,  g_wdef_t);
    cudaGetSymbolAddress((void**)&wtemp_t, g_wtemp_t);
    cudaGetSymbolAddress((void**)&offp,    g_off);
    cudaGetSymbolAddress((void**)&Bp,      g_B);

    // 1. transpose + pad weights to [R][256]
    transpose_pad<<<R5, 256>>>(w_off,  woff_t,  OFFC, R5);
    transpose_pad<<<R5, 256>>>(w_def,  wdef_t,  256,  R5);
    transpose_pad<<<R3, 256>>>(w_temp, wtemp_t, 256,  R3);

    // 2. offset conv: im2col 5x5 then GEMM -> g_off [t][och][p]
    im2col5_k<<<dim3(TT, CCH), 256>>>(x, Bp);
    gemm_k<<<dim3(36, TT, 2), 256>>>(woff_t, Bp, offp, R5, OFFC,
                                     PP, OFFC * PP, nullptr, 0);

    // 3. bilinear sampling -> g_B (reuse), deform GEMM -> out (write)
    sample_k<<<dim3(TT, 4, 25), 256>>>(x, offp, Bp);
    gemm_k<<<dim3(36, TT, 2), 256>>>(wdef_t, Bp, out, R5, 256,
                                     TT * PP, PP, nullptr, 0);

    // 4. temporal conv: im2col 3x3x3 -> g_B, GEMM accumulate + bias -> out
    im2col3_k<<<dim3(TT, CCH), 256>>>(x, Bp);
    gemm_k<<<dim3(36, TT, 2), 256>>>(wtemp_t, Bp, out, R3, 256,
                                     TT * PP, PP, b_temp, 1);
}

// round 4
// speedup vs baseline: 2.6827x; 2.6827x over previous
#include <cuda_runtime.h>
#include <cuda_bf16.h>
#include <cstdint>

#define TT   4
#define HH   48
#define WWD  48
#define PP   2304          // 48*48
#define R5   6400          // 256*25
#define R3   6912          // 256*27
#define OFFC 200           // 4*2*25

typedef __nv_bfloat16 bf16;

// ---------------- scratch (static device globals; no allocation) ----------------
__device__ bf16 g_Bh[(size_t)TT * PP * R3];   // [t][p][r] hi
__device__ bf16 g_Bl[(size_t)TT * PP * R3];   // [t][p][r] lo
__device__ bf16 g_Woff_h[256 * R5], g_Woff_l[256 * R5];
__device__ bf16 g_Wdef_h[256 * R5], g_Wdef_l[256 * R5];
__device__ bf16 g_Wtmp_h[256 * R3], g_Wtmp_l[256 * R3];
__device__ float g_off[TT * OFFC * PP];       // [t][och][p]

// ---------------- helpers ----------------
__device__ __forceinline__ uint32_t smem_u32(const void* p) {
    uint32_t a;
    asm("{ .reg .u64 t; cvta.to.shared.u64 t, %1; cvt.u32.u64 %0, t; }" : "=r"(a) : "l"(p));
    return a;
}
__device__ __forceinline__ void cpa16(uint32_t dst, const void* src) {
    asm volatile("cp.async.cg.shared.global [%0], [%1], 16;" :: "r"(dst), "l"(src) : "memory");
}
__device__ __forceinline__ void ldsm4(uint32_t* r, uint32_t a) {
    asm volatile("ldmatrix.sync.aligned.m8n8.x4.shared.b16 {%0,%1,%2,%3}, [%4];"
                 : "=r"(r[0]), "=r"(r[1]), "=r"(r[2]), "=r"(r[3]) : "r"(a));
}
__device__ __forceinline__ void mma16816(float* c, const uint32_t* a, const uint32_t* b) {
    asm volatile("mma.sync.aligned.m16n8k16.row.col.f32.bf16.bf16.f32 "
                 "{%0,%1,%2,%3}, {%4,%5,%6,%7}, {%8,%9}, {%0,%1,%2,%3};"
                 : "+f"(c[0]), "+f"(c[1]), "+f"(c[2]), "+f"(c[3])
                 : "r"(a[0]), "r"(a[1]), "r"(a[2]), "r"(a[3]), "r"(b[0]), "r"(b[1]));
}

// ---------------- weight split: src[O][R] fp32 -> hi/lo bf16, zero-pad O to 256 ----------------
__global__ void splitw_k(const float* __restrict__ src, bf16* __restrict__ h,
                         bf16* __restrict__ l, int O, int R) {
    int o = blockIdx.x;
    int r = blockIdx.y * 256 + threadIdx.x;
    float v = (o < O) ? src[(size_t)o * R + r] : 0.0f;
    bf16 hi = __float2bfloat16(v);
    h[(size_t)o * R + r] = hi;
    l[(size_t)o * R + r] = __float2bfloat16(v - __bfloat162float(hi));
}

// ---------------- im2col 1x5x5 pad2 -> B[t][p][r5] hi/lo (smem-staged transpose) ----------------
__global__ void __launch_bounds__(256) im2col5_k(const float* __restrict__ x,
                                                 bf16* __restrict__ Bh, bf16* __restrict__ Bl) {
    __shared__ float st[32][201];
    int t = blockIdx.x, p0 = blockIdx.y * 32, c0 = blockIdx.z * 8;
    int lane = threadIdx.x & 31, w = threadIdx.x >> 5;
    int c = c0 + w;
    int p = p0 + lane, py = p / WWD, px = p % WWD;
    const float* xs = x + ((size_t)c * TT + t) * PP;
    #pragma unroll
    for (int k = 0; k < 25; k++) {
        int y = py + k / 5 - 2, xx = px + k % 5 - 2;
        float v = (y >= 0 && y < HH && xx >= 0 && xx < WWD) ? xs[y * WWD + xx] : 0.0f;
        st[lane][w * 25 + k] = v;
    }
    __syncthreads();
    #pragma unroll
    for (int rr = 0; rr < 4; rr++) {
        int row = w * 4 + rr;
        size_t base = (size_t)(t * PP + p0 + row) * R5 + c0 * 25;
        for (int j = lane; j < 200; j += 32) {
            float v = st[row][j];
            bf16 hi = __float2bfloat16(v);
            Bh[base + j] = hi;
            Bl[base + j] = __float2bfloat16(v - __bfloat162float(hi));
        }
    }
}

// ---------------- im2col 3x3x3 pad1 -> B[t][p][r3] hi/lo ----------------
__global__ void __launch_bounds__(256) im2col3_k(const float* __restrict__ x,
                                                 bf16* __restrict__ Bh, bf16* __restrict__ Bl) {
    __shared__ float st[32][217];
    int t = blockIdx.x, p0 = blockIdx.y * 32, c0 = blockIdx.z * 8;
    int lane = threadIdx.x & 31, w = threadIdx.x >> 5;
    int c = c0 + w;
    int p = p0 + lane, py = p / WWD, px = p % WWD;
    const float* xc = x + (size_t)c * TT * PP;
    #pragma unroll
    for (int q = 0; q < 27; q++) {
        int kt = q / 9 - 1, rq = q % 9, ky = rq / 3 - 1, kx = rq % 3 - 1;
        int tt = t + kt, y = py + ky, xx = px + kx;
        float v = 0.0f;
        if (tt >= 0 && tt < TT && y >= 0 && y < HH && xx >= 0 && xx < WWD)
            v = xc[(size_t)tt * PP + y * WWD + xx];
        st[lane][w * 27 + q] = v;
    }
    __syncthreads();
    #pragma unroll
    for (int rr = 0; rr < 4; rr++) {
        int row = w * 4 + rr;
        size_t base = (size_t)(t * PP + p0 + row) * R3 + c0 * 27;
        for (int j = lane; j < 216; j += 32) {
            float v = st[row][j];
            bf16 hi = __float2bfloat16(v);
            Bh[base + j] = hi;
            Bl[base + j] = __float2bfloat16(v - __bfloat162float(hi));
        }
    }
}

// ---------------- bilinear sampler -> B[t][p][r5] hi/lo ----------------
__global__ void __launch_bounds__(256) sample_k(const float* __restrict__ x,
                                                const float* __restrict__ off,
                                                bf16* __restrict__ Bh, bf16* __restrict__ Bl) {
    __shared__ float st[32][201];
    int t = blockIdx.x, p0 = blockIdx.y * 32;
    int dg = blockIdx.z >> 3;
    int c0 = dg * 64 + (blockIdx.z & 7) * 8;
    int lane = threadIdx.x & 31, w = threadIdx.x >> 5;
    int c = c0 + w;
    int p = p0 + lane, py = p / WWD, px = p % WWD;
    const float* xc = x + ((size_t)c * TT + t) * PP;
    #pragma unroll
    for (int k = 0; k < 25; k++) {
        int ky = k / 5 - 2, kx = k % 5 - 2;
        const float* offy = off + ((size_t)t * OFFC + (dg * 25 + k) * 2) * PP;
        float sy = (float)(py + ky) + offy[p];
        float sx = (float)(px + kx) + offy[PP + p];
        float fy = floorf(sy), fx = floorf(sx);
        int y0 = (int)fy, x0 = (int)fx;
        float wy = sy - fy, wx = sx - fx;
        int y1 = y0 + 1, x1 = x0 + 1;
        float vy0 = (y0 >= 0 && y0 < HH) ? 1.0f : 0.0f;
        float vy1 = (y1 >= 0 && y1 < HH) ? 1.0f : 0.0f;
        float vx0 = (x0 >= 0 && x0 < WWD) ? 1.0f : 0.0f;
        float vx1 = (x1 >= 0 && x1 < WWD) ? 1.0f : 0.0f;
        int y0c = min(max(y0, 0), HH - 1), y1c = min(max(y1, 0), HH - 1);
        int x0c = min(max(x0, 0), WWD - 1), x1c = min(max(x1, 0), WWD - 1);
        float w00 = (1.0f - wy) * (1.0f - wx) * vy0 * vx0;
        float w01 = (1.0f - wy) * wx          * vy0 * vx1;
        float w10 = wy          * (1.0f - wx) * vy1 * vx0;
        float w11 = wy          * wx          * vy1 * vx1;
        float v = w00 * xc[y0c * WWD + x0c] + w01 * xc[y0c * WWD + x1c] +
                  w10 * xc[y1c * WWD + x0c] + w11 * xc[y1c * WWD + x1c];
        st[lane][w * 25 + k] = v;
    }
    __syncthreads();
    #pragma unroll
    for (int rr = 0; rr < 4; rr++) {
        int row = w * 4 + rr;
        size_t base = (size_t)(t * PP + p0 + row) * R5 + c0 * 25;
        for (int j = lane; j < 200; j += 32) {
            float v = st[row][j];
            bf16 hi = __float2bfloat16(v);
            Bh[base + j] = hi;
            Bl[base + j] = __float2bfloat16(v - __bfloat162float(hi));
        }
    }
}

// ---------------- split-bf16 3-pass mma.sync GEMM ----------------
// out[o][...] = sum_r W[o][r] * B[t][p][r];  tile 128(o) x 128(p), K chunk 32.
// Stage layout: Ah @0, Al @8192, Bh @16384, Bl @24576 (each 128 rows x 64B, XOR swizzle).
#define NSTAGE 3
#define STGSZ  32768
#define GSMEM  (NSTAGE * STGSZ)

__global__ void __launch_bounds__(256, 1) gemm_mma(
    const bf16* __restrict__ Wh, const bf16* __restrict__ Wl,
    const bf16* __restrict__ Bh, const bf16* __restrict__ Bl,
    float* __restrict__ outp, int R, int Olim,
    long long o_stride, long long t_stride,
    const float* __restrict__ bias, int accum)
{
    extern __shared__ char smraw[];
    uint32_t sb = smem_u32(smraw);
    int tid = threadIdx.x, lane = tid & 31, wid = tid >> 5;
    int wm = wid & 1, wn = wid >> 1;               // 2 x 4 warp grid -> 64x32 per warp
    int p0 = blockIdx.x * 128, t = blockIdx.y, o0 = blockIdx.z * 128;

    const bf16* gp[4];
    gp[0] = Wh + (size_t)o0 * R;
    gp[1] = Wl + (size_t)o0 * R;
    gp[2] = Bh + ((size_t)t * PP + p0) * R;
    gp[3] = Bl + ((size_t)t * PP + p0) * R;

    int lrow = tid >> 2;           // 0..63
    int lc   = tid & 3;            // 16B chunk within 64B row
    int NC = R >> 5;

    // ldmatrix per-lane row decomposition
    int aRow = (lane & 7) + ((lane >> 3) & 1) * 8;  // A: within m16 tile
    int aKg  = (lane >> 4) & 1;
    int bRow = (lane & 7) + ((lane >> 4) & 1) * 8;  // B: within n16 (2 tiles)
    int bKg  = (lane >> 3) & 1;

    float acc[4][4][4];
    #pragma unroll
    for (int i = 0; i < 4; i++)
        #pragma unroll
        for (int j = 0; j < 4; j++)
            #pragma unroll
            for (int q = 0; q < 4; q++) acc[i][j][q] = 0.0f;

    // prologue: load chunks 0,1
    #pragma unroll
    for (int pc = 0; pc < 2; pc++) {
        uint32_t stb = sb + pc * STGSZ;
        size_t rof = (size_t)(pc * 32) + lc * 8;
        #pragma unroll
        for (int tl = 0; tl < 4; tl++) {
            uint32_t dst = stb + tl * 8192;
            #pragma unroll
            for (int h = 0; h < 2; h++) {
                int row = lrow + h * 64;
                cpa16(dst + row * 64 + ((lc ^ ((row >> 1) & 3)) << 4),
                      gp[tl] + (size_t)row * R + rof);
            }
        }
        asm volatile("cp.async.commit_group;" ::: "memory");
    }

    for (int ch = 0; ch < NC; ch++) {
        asm volatile("cp.async.wait_group 1;" ::: "memory");
        __syncthreads();
        uint32_t stb = sb + (ch % NSTAGE) * STGSZ;

        #pragma unroll
        for (int kh = 0; kh < 2; kh++) {
            int kc = kh * 2;
            uint32_t ah[4][4], al[4][4], bh[4][2], bl[4][2];
            #pragma unroll
            for (int mt = 0; mt < 4; mt++) {
                int row = wm * 64 + mt * 16 + aRow;
                uint32_t ad = stb + row * 64 + (((kc + aKg) ^ ((row >> 1) & 3)) << 4);
                ldsm4(ah[mt], ad);
                ldsm4(al[mt], ad + 8192);
            }
            #pragma unroll
            for (int ng = 0; ng < 2; ng++) {
                int row = wn * 32 + ng * 16 + bRow;
                uint32_t bd = stb + 16384 + row * 64 + (((kc + bKg) ^ ((row >> 1) & 3)) << 4);
                uint32_t r4[4];
                ldsm4(r4, bd);
                bh[ng * 2][0] = r4[0]; bh[ng * 2][1] = r4[1];
                bh[ng * 2 + 1][0] = r4[2]; bh[ng * 2 + 1][1] = r4[3];
                ldsm4(r4, bd + 8192);
                bl[ng * 2][0] = r4[0]; bl[ng * 2][1] = r4[1];
                bl[ng * 2 + 1][0] = r4[2]; bl[ng * 2 + 1][1] = r4[3];
            }
            #pragma unroll
            for (int mt = 0; mt < 4; mt++)
                #pragma unroll
                for (int nt = 0; nt < 4; nt++) {
                    mma16816(acc[mt][nt], ah[mt], bh[nt]);
                    mma16816(acc[mt][nt], ah[mt], bl[nt]);
                    mma16816(acc[mt][nt], al[mt], bh[nt]);
                }
        }

        int nx = ch + 2;
        if (nx < NC) {
            uint32_t stb2 = sb + (nx % NSTAGE) * STGSZ;
            size_t rof = (size_t)(nx * 32) + lc * 8;
            #pragma unroll
            for (int tl = 0; tl < 4; tl++) {
                uint32_t dst = stb2 + tl * 8192;
                #pragma unroll
                for (int h = 0; h < 2; h++) {
                    int row = lrow + h * 64;
                    cpa16(dst + row * 64 + ((lc ^ ((row >> 1) & 3)) << 4),
                          gp[tl] + (size_t)row * R + rof);
                }
            }
        }
        asm volatile("cp.async.commit_group;" ::: "memory");
    }

    // epilogue
    int er = lane >> 2, ec = (lane & 3) * 2;
    #pragma unroll
    for (int mt = 0; mt < 4; mt++) {
        int obase = o0 + wm * 64 + mt * 16 + er;
        #pragma unroll
        for (int h = 0; h < 2; h++) {
            int o = obase + h * 8;
            if (o < Olim) {
                float bv = (bias != nullptr) ? bias[o] : 0.0f;
                size_t rb = (size_t)o * o_stride + (size_t)t * t_stride + p0 + wn * 32 + ec;
                #pragma unroll
                for (int nt = 0; nt < 4; nt++) {
                    float2* dp = (float2*)(outp + rb + nt * 8);
                    float v0 = acc[mt][nt][h * 2 + 0] + bv;
                    float v1 = acc[mt][nt][h * 2 + 1] + bv;
                    if (accum) { float2 old = *dp; v0 += old.x; v1 += old.y; }
                    float2 wv; wv.x = v0; wv.y = v1;
                    *dp = wv;
                }
            }
        }
    }
}

// ---------------- launch ----------------
extern "C" void kernel_launch(void* const* d_in, const int* in_sizes, int n_in,
                              void* d_out, int out_size) {
    (void)in_sizes; (void)n_in; (void)out_size;
    const float* x      = (const float*)d_in[0];
    const float* w_off  = (const float*)d_in[1];
    const float* w_def  = (const float*)d_in[2];
    const float* w_temp = (const float*)d_in[3];
    const float* b_temp = (const float*)d_in[4];
    float* out = (float*)d_out;

    bf16 *Bhp, *Blp, *wofh, *wofl, *wdfh, *wdfl, *wtph, *wtpl;
    float* offp;
    cudaGetSymbolAddress((void**)&Bhp,  g_Bh);
    cudaGetSymbolAddress((void**)&Blp,  g_Bl);
    cudaGetSymbolAddress((void**)&wofh, g_Woff_h);
    cudaGetSymbolAddress((void**)&wofl, g_Woff_l);
    cudaGetSymbolAddress((void**)&wdfh, g_Wdef_h);
    cudaGetSymbolAddress((void**)&wdfl, g_Wdef_l);
    cudaGetSymbolAddress((void**)&wtph, g_Wtmp_h);
    cudaGetSymbolAddress((void**)&wtpl, g_Wtmp_l);
    cudaGetSymbolAddress((void**)&offp, g_off);

    cudaFuncSetAttribute(gemm_mma, cudaFuncAttributeMaxDynamicSharedMemorySize, GSMEM);

    // weight splits
    splitw_k<<<dim3(256, 25), 256>>>(w_off,  wofh, wofl, OFFC, R5);
    splitw_k<<<dim3(256, 25), 256>>>(w_def,  wdfh, wdfl, 256,  R5);
    splitw_k<<<dim3(256, 27), 256>>>(w_temp, wtph, wtpl, 256,  R3);

    // offset conv
    im2col5_k<<<dim3(TT, 72, 32), 256>>>(x, Bhp, Blp);
    gemm_mma<<<dim3(18, TT, 2), 256, GSMEM>>>(wofh, wofl, Bhp, Blp, offp, R5, OFFC,
                                              PP, (long long)OFFC * PP, nullptr, 0);

    // deformable conv
    sample_k<<<dim3(TT, 72, 32), 256>>>(x, offp, Bhp, Blp);
    gemm_mma<<<dim3(18, TT, 2), 256, GSMEM>>>(wdfh, wdfl, Bhp, Blp, out, R5, 256,
                                              (long long)TT * PP, PP, nullptr, 0);

    // temporal conv (accumulate + bias)
    im2col3_k<<<dim3(TT, 72, 32), 256>>>(x, Bhp, Blp);
    gemm_mma<<<dim3(18, TT, 2), 256, GSMEM>>>(wtph, wtpl, Bhp, Blp, out, R3, 256,
                                              (long long)TT * PP, PP, b_temp, 1);
}

// round 5
// speedup vs baseline: 3.7395x; 1.3939x over previous
#include <cuda_runtime.h>
#include <cuda_fp16.h>
#include <cstdint>

#define TT   4
#define HH   48
#define WWD  48
#define PP   2304          // 48*48
#define R5   6400          // 256*25
#define R3   6912          // 256*27
#define RF   13312         // R5 + R3 fused K
#define OFFC 200           // 4*2*25

typedef __half fp16;

// ---------------- scratch (static device globals; no allocation) ----------------
__device__ fp16 g_B5[(size_t)TT * PP * R5];   // [t][p][r5]   im2col5 of x (offset conv B)
__device__ fp16 g_Bf[(size_t)TT * PP * RF];   // [t][p][rf]   sampler(0..6400) + im2col3(6400..)
__device__ fp16 g_Woff_h[256 * R5], g_Woff_l[256 * R5];
__device__ fp16 g_Wf_h[256 * RF],  g_Wf_l[256 * RF];
__device__ float g_off[TT * OFFC * PP];       // [t][och][p]

// ---------------- helpers ----------------
__device__ __forceinline__ uint32_t smem_u32(const void* p) {
    uint32_t a;
    asm("{ .reg .u64 t; cvta.to.shared.u64 t, %1; cvt.u32.u64 %0, t; }" : "=r"(a) : "l"(p));
    return a;
}
__device__ __forceinline__ void cpa16(uint32_t dst, const void* src) {
    asm volatile("cp.async.cg.shared.global [%0], [%1], 16;" :: "r"(dst), "l"(src) : "memory");
}
__device__ __forceinline__ void ldsm4(uint32_t* r, uint32_t a) {
    asm volatile("ldmatrix.sync.aligned.m8n8.x4.shared.b16 {%0,%1,%2,%3}, [%4];"
                 : "=r"(r[0]), "=r"(r[1]), "=r"(r[2]), "=r"(r[3]) : "r"(a));
}
__device__ __forceinline__ void mma16816(float* c, const uint32_t* a, const uint32_t* b) {
    asm volatile("mma.sync.aligned.m16n8k16.row.col.f32.f16.f16.f32 "
                 "{%0,%1,%2,%3}, {%4,%5,%6,%7}, {%8,%9}, {%0,%1,%2,%3};"
                 : "+f"(c[0]), "+f"(c[1]), "+f"(c[2]), "+f"(c[3])
                 : "r"(a[0]), "r"(a[1]), "r"(a[2]), "r"(a[3]), "r"(b[0]), "r"(b[1]));
}
__device__ __forceinline__ void split16(float v, fp16& h, fp16& l) {
    h = __float2half_rn(v);
    l = __float2half_rn(v - __half2float(h));
}

// ---------------- weight split (offset conv): w_off[O][R5] -> hi/lo, pad O to 256 ----------------
__global__ void splitw_off(const float* __restrict__ src, fp16* __restrict__ h,
                           fp16* __restrict__ l) {
    int o = blockIdx.x;
    int r = blockIdx.y * 256 + threadIdx.x;
    float v = (o < OFFC) ? src[(size_t)o * R5 + r] : 0.0f;
    fp16 hi, lo; split16(v, hi, lo);
    h[(size_t)o * R5 + r] = hi;
    l[(size_t)o * R5 + r] = lo;
}

// ---------------- weight split (fused): [w_def | w_temp] -> hi/lo over RF ----------------
__global__ void splitw_f(const float* __restrict__ wdef, const float* __restrict__ wtmp,
                         fp16* __restrict__ h, fp16* __restrict__ l) {
    int o = blockIdx.x;
    int r = blockIdx.y * 256 + threadIdx.x;
    float v = (r < R5) ? wdef[(size_t)o * R5 + r] : wtmp[(size_t)o * R3 + (r - R5)];
    fp16 hi, lo; split16(v, hi, lo);
    h[(size_t)o * RF + r] = hi;
    l[(size_t)o * RF + r] = lo;
}

// ---------------- im2col 1x5x5 pad2 -> B5[t][p][r5] fp16 (smem-staged transpose) ----------------
__global__ void __launch_bounds__(256) im2col5_k(const float* __restrict__ x,
                                                 fp16* __restrict__ B) {
    __shared__ float st[32][201];
    int t = blockIdx.x, p0 = blockIdx.y * 32, c0 = blockIdx.z * 8;
    int lane = threadIdx.x & 31, w = threadIdx.x >> 5;
    int c = c0 + w;
    int p = p0 + lane, py = p / WWD, px = p % WWD;
    const float* xs = x + ((size_t)c * TT + t) * PP;
    #pragma unroll
    for (int k = 0; k < 25; k++) {
        int y = py + k / 5 - 2, xx = px + k % 5 - 2;
        float v = (y >= 0 && y < HH && xx >= 0 && xx < WWD) ? xs[y * WWD + xx] : 0.0f;
        st[lane][w * 25 + k] = v;
    }
    __syncthreads();
    #pragma unroll
    for (int rr = 0; rr < 4; rr++) {
        int row = w * 4 + rr;
        size_t base = (size_t)(t * PP + p0 + row) * R5 + c0 * 25;
        for (int j = lane; j < 200; j += 32)
            B[base + j] = __float2half_rn(st[row][j]);
    }
}

// ---------------- im2col 3x3x3 pad1 -> Bf[t][p][6400 + r3] fp16 ----------------
__global__ void __launch_bounds__(256) im2col3_k(const float* __restrict__ x,
                                                 fp16* __restrict__ B) {
    __shared__ float st[32][217];
    int t = blockIdx.x, p0 = blockIdx.y * 32, c0 = blockIdx.z * 8;
    int lane = threadIdx.x & 31, w = threadIdx.x >> 5;
    int c = c0 + w;
    int p = p0 + lane, py = p / WWD, px = p % WWD;
    const float* xc = x + (size_t)c * TT * PP;
    #pragma unroll
    for (int q = 0; q < 27; q++) {
        int kt = q / 9 - 1, rq = q % 9, ky = rq / 3 - 1, kx = rq % 3 - 1;
        int tt = t + kt, y = py + ky, xx = px + kx;
        float v = 0.0f;
        if (tt >= 0 && tt < TT && y >= 0 && y < HH && xx >= 0 && xx < WWD)
            v = xc[(size_t)tt * PP + y * WWD + xx];
        st[lane][w * 27 + q] = v;
    }
    __syncthreads();
    #pragma unroll
    for (int rr = 0; rr < 4; rr++) {
        int row = w * 4 + rr;
        size_t base = (size_t)(t * PP + p0 + row) * RF + R5 + c0 * 27;
        for (int j = lane; j < 216; j += 32)
            B[base + j] = __float2half_rn(st[row][j]);
    }
}

// ---------------- bilinear sampler -> Bf[t][p][r5] fp16 ----------------
__global__ void __launch_bounds__(256) sample_k(const float* __restrict__ x,
                                                const float* __restrict__ off,
                                                fp16* __restrict__ B) {
    __shared__ float st[32][201];
    int t = blockIdx.x, p0 = blockIdx.y * 32;
    int dg = blockIdx.z >> 3;
    int c0 = dg * 64 + (blockIdx.z & 7) * 8;
    int lane = threadIdx.x & 31, w = threadIdx.x >> 5;
    int c = c0 + w;
    int p = p0 + lane, py = p / WWD, px = p % WWD;
    const float* xc = x + ((size_t)c * TT + t) * PP;
    #pragma unroll
    for (int k = 0; k < 25; k++) {
        int ky = k / 5 - 2, kx = k % 5 - 2;
        const float* offy = off + ((size_t)t * OFFC + (dg * 25 + k) * 2) * PP;
        float sy = (float)(py + ky) + offy[p];
        float sx = (float)(px + kx) + offy[PP + p];
        float fy = floorf(sy), fx = floorf(sx);
        int y0 = (int)fy, x0 = (int)fx;
        float wy = sy - fy, wx = sx - fx;
        int y1 = y0 + 1, x1 = x0 + 1;
        float vy0 = (y0 >= 0 && y0 < HH) ? 1.0f : 0.0f;
        float vy1 = (y1 >= 0 && y1 < HH) ? 1.0f : 0.0f;
        float vx0 = (x0 >= 0 && x0 < WWD) ? 1.0f : 0.0f;
        float vx1 = (x1 >= 0 && x1 < WWD) ? 1.0f : 0.0f;
        int y0c = min(max(y0, 0), HH - 1), y1c = min(max(y1, 0), HH - 1);
        int x0c = min(max(x0, 0), WWD - 1), x1c = min(max(x1, 0), WWD - 1);
        float w00 = (1.0f - wy) * (1.0f - wx) * vy0 * vx0;
        float w01 = (1.0f - wy) * wx          * vy0 * vx1;
        float w10 = wy          * (1.0f - wx) * vy1 * vx0;
        float w11 = wy          * wx          * vy1 * vx1;
        float v = w00 * xc[y0c * WWD + x0c] + w01 * xc[y0c * WWD + x1c] +
                  w10 * xc[y1c * WWD + x0c] + w11 * xc[y1c * WWD + x1c];
        st[lane][w * 25 + k] = v;
    }
    __syncthreads();
    #pragma unroll
    for (int rr = 0; rr < 4; rr++) {
        int row = w * 4 + rr;
        size_t base = (size_t)(t * PP + p0 + row) * RF + c0 * 25;
        for (int j = lane; j < 200; j += 32)
            B[base + j] = __float2half_rn(st[row][j]);
    }
}

// ---------------- 2-pass split-fp16 mma.sync GEMM ----------------
// out[o][...] = sum_r (Wh+Wl)[o][r] * Bh[t][p][r];  tile 128(o) x 128(p), K chunk 32.
// Stage: Ah @0, Al @8192, Bh @16384 (each 128 rows x 64B, XOR swizzle). 4 stages.
#define NSTAGE 4
#define STGSZ  24576
#define GSMEM  (NSTAGE * STGSZ)

__global__ void __launch_bounds__(256, 1) gemm_mma(
    const fp16* __restrict__ Wh, const fp16* __restrict__ Wl,
    const fp16* __restrict__ Bh,
    float* __restrict__ outp, int R, int Olim,
    long long o_stride, long long t_stride,
    const float* __restrict__ bias)
{
    extern __shared__ char smraw[];
    uint32_t sb = smem_u32(smraw);
    int tid = threadIdx.x, lane = tid & 31, wid = tid >> 5;
    int wm = wid & 1, wn = wid >> 1;               // 2 x 4 warp grid -> 64x32 per warp
    int p0 = blockIdx.x * 128, t = blockIdx.y, o0 = blockIdx.z * 128;

    const fp16* gp[3];
    gp[0] = Wh + (size_t)o0 * R;
    gp[1] = Wl + (size_t)o0 * R;
    gp[2] = Bh + ((size_t)t * PP + p0) * R;

    int lrow = tid >> 2;           // 0..63
    int lc   = tid & 3;            // 16B chunk within 64B row
    int NC = R >> 5;

    int aRow = (lane & 7) + ((lane >> 3) & 1) * 8;  // A: within m16 tile
    int aKg  = (lane >> 4) & 1;
    int bRow = (lane & 7) + ((lane >> 4) & 1) * 8;  // B: within n16 (2 tiles)
    int bKg  = (lane >> 3) & 1;

    float acc[4][4][4];
    #pragma unroll
    for (int i = 0; i < 4; i++)
        #pragma unroll
        for (int j = 0; j < 4; j++)
            #pragma unroll
            for (int q = 0; q < 4; q++) acc[i][j][q] = 0.0f;

    // prologue: load chunks 0..2
    #pragma unroll
    for (int pc = 0; pc < NSTAGE - 1; pc++) {
        uint32_t stb = sb + pc * STGSZ;
        size_t rof = (size_t)(pc * 32) + lc * 8;
        #pragma unroll
        for (int tl = 0; tl < 3; tl++) {
            uint32_t dst = stb + tl * 8192;
            #pragma unroll
            for (int h = 0; h < 2; h++) {
                int row = lrow + h * 64;
                cpa16(dst + row * 64 + ((lc ^ ((row >> 1) & 3)) << 4),
                      gp[tl] + (size_t)row * R + rof);
            }
        }
        asm volatile("cp.async.commit_group;" ::: "memory");
    }

    for (int ch = 0; ch < NC; ch++) {
        asm volatile("cp.async.wait_group 2;" ::: "memory");
        __syncthreads();
        uint32_t stb = sb + (ch % NSTAGE) * STGSZ;

        #pragma unroll
        for (int kh = 0; kh < 2; kh++) {
            int kc = kh * 2;
            uint32_t ah[4][4], al[4][4], bh[4][2];
            #pragma unroll
            for (int mt = 0; mt < 4; mt++) {
                int row = wm * 64 + mt * 16 + aRow;
                uint32_t ad = stb + row * 64 + (((kc + aKg) ^ ((row >> 1) & 3)) << 4);
                ldsm4(ah[mt], ad);
                ldsm4(al[mt], ad + 8192);
            }
            #pragma unroll
            for (int ng = 0; ng < 2; ng++) {
                int row = wn * 32 + ng * 16 + bRow;
                uint32_t bd = stb + 16384 + row * 64 + (((kc + bKg) ^ ((row >> 1) & 3)) << 4);
                uint32_t r4[4];
                ldsm4(r4, bd);
                bh[ng * 2][0] = r4[0]; bh[ng * 2][1] = r4[1];
                bh[ng * 2 + 1][0] = r4[2]; bh[ng * 2 + 1][1] = r4[3];
            }
            #pragma unroll
            for (int mt = 0; mt < 4; mt++)
                #pragma unroll
                for (int nt = 0; nt < 4; nt++) {
                    mma16816(acc[mt][nt], ah[mt], bh[nt]);
                    mma16816(acc[mt][nt], al[mt], bh[nt]);
                }
        }

        int nx = ch + NSTAGE - 1;
        if (nx < NC) {
            uint32_t stb2 = sb + (nx % NSTAGE) * STGSZ;
            size_t rof = (size_t)(nx * 32) + lc * 8;
            #pragma unroll
            for (int tl = 0; tl < 3; tl++) {
                uint32_t dst = stb2 + tl * 8192;
                #pragma unroll
                for (int h = 0; h < 2; h++) {
                    int row = lrow + h * 64;
                    cpa16(dst + row * 64 + ((lc ^ ((row >> 1) & 3)) << 4),
                          gp[tl] + (size_t)row * R + rof);
                }
            }
        }
        asm volatile("cp.async.commit_group;" ::: "memory");
    }

    // epilogue
    int er = lane >> 2, ec = (lane & 3) * 2;
    #pragma unroll
    for (int mt = 0; mt < 4; mt++) {
        int obase = o0 + wm * 64 + mt * 16 + er;
        #pragma unroll
        for (int h = 0; h < 2; h++) {
            int o = obase + h * 8;
            if (o < Olim) {
                float bv = (bias != nullptr) ? bias[o] : 0.0f;
                size_t rb = (size_t)o * o_stride + (size_t)t * t_stride + p0 + wn * 32 + ec;
                #pragma unroll
                for (int nt = 0; nt < 4; nt++) {
                    float2* dp = (float2*)(outp + rb + nt * 8);
                    float2 wv;
                    wv.x = acc[mt][nt][h * 2 + 0] + bv;
                    wv.y = acc[mt][nt][h * 2 + 1] + bv;
                    *dp = wv;
                }
            }
        }
    }
}

// ---------------- launch ----------------
extern "C" void kernel_launch(void* const* d_in, const int* in_sizes, int n_in,
                              void* d_out, int out_size) {
    (void)in_sizes; (void)n_in; (void)out_size;
    const float* x      = (const float*)d_in[0];
    const float* w_off  = (const float*)d_in[1];
    const float* w_def  = (const float*)d_in[2];
    const float* w_temp = (const float*)d_in[3];
    const float* b_temp = (const float*)d_in[4];
    float* out = (float*)d_out;

    fp16 *B5p, *Bfp, *wofh, *wofl, *wfh, *wfl;
    float* offp;
    cudaGetSymbolAddress((void**)&B5p,  g_B5);
    cudaGetSymbolAddress((void**)&Bfp,  g_Bf);
    cudaGetSymbolAddress((void**)&wofh, g_Woff_h);
    cudaGetSymbolAddress((void**)&wofl, g_Woff_l);
    cudaGetSymbolAddress((void**)&wfh,  g_Wf_h);
    cudaGetSymbolAddress((void**)&wfl,  g_Wf_l);
    cudaGetSymbolAddress((void**)&offp, g_off);

    cudaFuncSetAttribute(gemm_mma, cudaFuncAttributeMaxDynamicSharedMemorySize, GSMEM);

    // weight splits
    splitw_off<<<dim3(256, 25), 256>>>(w_off, wofh, wofl);
    splitw_f  <<<dim3(256, 52), 256>>>(w_def, w_temp, wfh, wfl);

    // temporal im2col (independent of offset path) -> fused B, cols [6400, 13312)
    im2col3_k<<<dim3(TT, 72, 32), 256>>>(x, Bfp);

    // offset conv: im2col5 -> B5, GEMM -> g_off
    im2col5_k<<<dim3(TT, 72, 32), 256>>>(x, B5p);
    gemm_mma<<<dim3(18, TT, 2), 256, GSMEM>>>(wofh, wofl, B5p, offp, R5, OFFC,
                                              PP, (long long)OFFC * PP, nullptr);

    // bilinear sampling -> fused B, cols [0, 6400)
    sample_k<<<dim3(TT, 72, 32), 256>>>(x, offp, Bfp);

    // fused deform + temporal GEMM (bias folded in)
    gemm_mma<<<dim3(18, TT, 2), 256, GSMEM>>>(wfh, wfl, Bfp, out, RF, 256,
                                              (long long)TT * PP, PP, b_temp);
}

// round 6
// speedup vs baseline: 4.1566x; 1.1115x over previous
#include <cuda_runtime.h>
#include <cuda_fp16.h>
#include <cstdint>

#define TT   4
#define HH   48
#define WWD  48
#define PP   2304          // 48*48
#define R5   6400          // 256*25
#define R3   6912          // 256*27
#define RF   13312         // R5 + R3 fused K
#define OFFC 200           // 4*2*25

typedef __half fp16;

// ---------------- scratch (static device globals; no allocation) ----------------
__device__ fp16 g_B5[(size_t)TT * PP * R5];   // [t][p][r5]   im2col5 of x (offset conv B)
__device__ fp16 g_Bf[(size_t)TT * PP * RF];   // [t][p][rf]   sampler(0..6400) + im2col3(6400..)
__device__ fp16 g_Woff_h[256 * R5];
__device__ fp16 g_Wf_h[256 * RF], g_Wf_l[256 * RF];
__device__ float g_off[TT * OFFC * PP];       // [t][och][p]

// ---------------- helpers ----------------
__device__ __forceinline__ uint32_t smem_u32(const void* p) {
    uint32_t a;
    asm("{ .reg .u64 t; cvta.to.shared.u64 t, %1; cvt.u32.u64 %0, t; }" : "=r"(a) : "l"(p));
    return a;
}
__device__ __forceinline__ void cpa16(uint32_t dst, const void* src) {
    asm volatile("cp.async.cg.shared.global [%0], [%1], 16;" :: "r"(dst), "l"(src) : "memory");
}
__device__ __forceinline__ void ldsm4(uint32_t* r, uint32_t a) {
    asm volatile("ldmatrix.sync.aligned.m8n8.x4.shared.b16 {%0,%1,%2,%3}, [%4];"
                 : "=r"(r[0]), "=r"(r[1]), "=r"(r[2]), "=r"(r[3]) : "r"(a));
}
__device__ __forceinline__ void mma16816(float* c, const uint32_t* a, const uint32_t* b) {
    asm volatile("mma.sync.aligned.m16n8k16.row.col.f32.f16.f16.f32 "
                 "{%0,%1,%2,%3}, {%4,%5,%6,%7}, {%8,%9}, {%0,%1,%2,%3};"
                 : "+f"(c[0]), "+f"(c[1]), "+f"(c[2]), "+f"(c[3])
                 : "r"(a[0]), "r"(a[1]), "r"(a[2]), "r"(a[3]), "r"(b[0]), "r"(b[1]));
}

// ---------------- weight split (offset conv): hi only, pad O to 256 ----------------
__global__ void splitw_off(const float* __restrict__ src, fp16* __restrict__ h) {
    int o = blockIdx.x;
    int r = blockIdx.y * 256 + threadIdx.x;
    float v = (o < OFFC) ? src[(size_t)o * R5 + r] : 0.0f;
    h[(size_t)o * R5 + r] = __float2half_rn(v);
}

// ---------------- weight split (fused): [w_def | w_temp] -> hi/lo over RF ----------------
__global__ void splitw_f(const float* __restrict__ wdef, const float* __restrict__ wtmp,
                         fp16* __restrict__ h, fp16* __restrict__ l) {
    int o = blockIdx.x;
    int r = blockIdx.y * 256 + threadIdx.x;
    float v = (r < R5) ? wdef[(size_t)o * R5 + r] : wtmp[(size_t)o * R3 + (r - R5)];
    fp16 hi = __float2half_rn(v);
    h[(size_t)o * RF + r] = hi;
    l[(size_t)o * RF + r] = __float2half_rn(v - __half2float(hi));
}

// ---------------- im2col 1x5x5 pad2 -> B5[t][p][r5] fp16 ----------------
__global__ void __launch_bounds__(256) im2col5_k(const float* __restrict__ x,
                                                 fp16* __restrict__ B) {
    __shared__ float st[32][201];
    int t = blockIdx.x, p0 = blockIdx.y * 32, c0 = blockIdx.z * 8;
    int lane = threadIdx.x & 31, w = threadIdx.x >> 5;
    int c = c0 + w;
    int p = p0 + lane, py = p / WWD, px = p % WWD;
    const float* xs = x + ((size_t)c * TT + t) * PP;
    #pragma unroll
    for (int k = 0; k < 25; k++) {
        int y = py + k / 5 - 2, xx = px + k % 5 - 2;
        float v = (y >= 0 && y < HH && xx >= 0 && xx < WWD) ? xs[y * WWD + xx] : 0.0f;
        st[lane][w * 25 + k] = v;
    }
    __syncthreads();
    #pragma unroll
    for (int rr = 0; rr < 4; rr++) {
        int row = w * 4 + rr;
        size_t base = (size_t)(t * PP + p0 + row) * R5 + c0 * 25;
        for (int j = lane; j < 200; j += 32)
            B[base + j] = __float2half_rn(st[row][j]);
    }
}

// ---------------- im2col 3x3x3 pad1 -> Bf[t][p][6400 + r3] fp16 ----------------
__global__ void __launch_bounds__(256) im2col3_k(const float* __restrict__ x,
                                                 fp16* __restrict__ B) {
    __shared__ float st[32][217];
    int t = blockIdx.x, p0 = blockIdx.y * 32, c0 = blockIdx.z * 8;
    int lane = threadIdx.x & 31, w = threadIdx.x >> 5;
    int c = c0 + w;
    int p = p0 + lane, py = p / WWD, px = p % WWD;
    const float* xc = x + (size_t)c * TT * PP;
    #pragma unroll
    for (int q = 0; q < 27; q++) {
        int kt = q / 9 - 1, rq = q % 9, ky = rq / 3 - 1, kx = rq % 3 - 1;
        int tt = t + kt, y = py + ky, xx = px + kx;
        float v = 0.0f;
        if (tt >= 0 && tt < TT && y >= 0 && y < HH && xx >= 0 && xx < WWD)
            v = xc[(size_t)tt * PP + y * WWD + xx];
        st[lane][w * 27 + q] = v;
    }
    __syncthreads();
    #pragma unroll
    for (int rr = 0; rr < 4; rr++) {
        int row = w * 4 + rr;
        size_t base = (size_t)(t * PP + p0 + row) * RF + R5 + c0 * 27;
        for (int j = lane; j < 216; j += 32)
            B[base + j] = __float2half_rn(st[row][j]);
    }
}

// ---------------- bilinear sampler -> Bf[t][p][r5] fp16 ----------------
__global__ void __launch_bounds__(256) sample_k(const float* __restrict__ x,
                                                const float* __restrict__ off,
                                                fp16* __restrict__ B) {
    __shared__ float st[32][201];
    int t = blockIdx.x, p0 = blockIdx.y * 32;
    int dg = blockIdx.z >> 3;
    int c0 = dg * 64 + (blockIdx.z & 7) * 8;
    int lane = threadIdx.x & 31, w = threadIdx.x >> 5;
    int c = c0 + w;
    int p = p0 + lane, py = p / WWD, px = p % WWD;
    const float* xc = x + ((size_t)c * TT + t) * PP;
    #pragma unroll
    for (int k = 0; k < 25; k++) {
        int ky = k / 5 - 2, kx = k % 5 - 2;
        const float* offy = off + ((size_t)t * OFFC + (dg * 25 + k) * 2) * PP;
        float sy = (float)(py + ky) + offy[p];
        float sx = (float)(px + kx) + offy[PP + p];
        float fy = floorf(sy), fx = floorf(sx);
        int y0 = (int)fy, x0 = (int)fx;
        float wy = sy - fy, wx = sx - fx;
        int y1 = y0 + 1, x1 = x0 + 1;
        float vy0 = (y0 >= 0 && y0 < HH) ? 1.0f : 0.0f;
        float vy1 = (y1 >= 0 && y1 < HH) ? 1.0f : 0.0f;
        float vx0 = (x0 >= 0 && x0 < WWD) ? 1.0f : 0.0f;
        float vx1 = (x1 >= 0 && x1 < WWD) ? 1.0f : 0.0f;
        int y0c = min(max(y0, 0), HH - 1), y1c = min(max(y1, 0), HH - 1);
        int x0c = min(max(x0, 0), WWD - 1), x1c = min(max(x1, 0), WWD - 1);
        float w00 = (1.0f - wy) * (1.0f - wx) * vy0 * vx0;
        float w01 = (1.0f - wy) * wx          * vy0 * vx1;
        float w10 = wy          * (1.0f - wx) * vy1 * vx0;
        float w11 = wy          * wx          * vy1 * vx1;
        float v = w00 * xc[y0c * WWD + x0c] + w01 * xc[y0c * WWD + x1c] +
                  w10 * xc[y1c * WWD + x0c] + w11 * xc[y1c * WWD + x1c];
        st[lane][w * 25 + k] = v;
    }
    __syncthreads();
    #pragma unroll
    for (int rr = 0; rr < 4; rr++) {
        int row = w * 4 + rr;
        size_t base = (size_t)(t * PP + p0 + row) * RF + c0 * 25;
        for (int j = lane; j < 200; j += 32)
            B[base + j] = __float2half_rn(st[row][j]);
    }
}

// ---------------- split-fp16 mma.sync GEMM (TILES=2: 1-pass, TILES=3: 2-pass) ----------------
// Tile 128(o) x 128(p), K chunk 32, 4 stages. Warp grid 4(m) x 2(n): warp tile 32x64.
// Stage layout: Ah @0, B @8192, [Al @16384]. XOR swizzle, all conflict-free.
#define NSTAGE 4

template<int TILES>
__global__ void __launch_bounds__(256, 1) gemm_mma(
    const fp16* __restrict__ Wh, const fp16* __restrict__ Wl,
    const fp16* __restrict__ Bh,
    float* __restrict__ outp, int R, int Olim,
    long long o_stride, long long t_stride,
    const float* __restrict__ bias)
{
    const int STG = TILES * 8192;
    extern __shared__ char smraw[];
    uint32_t sb = smem_u32(smraw);
    int tid = threadIdx.x, lane = tid & 31, wid = tid >> 5;
    int wm = wid & 3, wn = wid >> 2;               // 4 x 2 warp grid -> 32x64 per warp
    int p0 = blockIdx.x * 128, t = blockIdx.y, o0 = blockIdx.z * 128;

    const fp16* gp[3];
    gp[0] = Wh + (size_t)o0 * R;
    gp[1] = Bh + ((size_t)t * PP + p0) * R;
    gp[2] = Wl + (size_t)o0 * R;

    int lrow = tid >> 2;           // 0..63
    int lc   = tid & 3;            // 16B chunk within 64B row
    int NC = R >> 5;

    int aRow = (lane & 7) + ((lane >> 3) & 1) * 8;  // A: within m16 tile
    int aKg  = (lane >> 4) & 1;
    int bRow = (lane & 7) + ((lane >> 4) & 1) * 8;  // B: within n16 (2 tiles)
    int bKg  = (lane >> 3) & 1;

    float acc[2][8][4];
    #pragma unroll
    for (int i = 0; i < 2; i++)
        #pragma unroll
        for (int j = 0; j < 8; j++)
            #pragma unroll
            for (int q = 0; q < 4; q++) acc[i][j][q] = 0.0f;

    // prologue: load chunks 0..NSTAGE-2
    #pragma unroll
    for (int pc = 0; pc < NSTAGE - 1; pc++) {
        uint32_t stb = sb + pc * STG;
        size_t rof = (size_t)(pc * 32) + lc * 8;
        #pragma unroll
        for (int tl = 0; tl < TILES; tl++) {
            uint32_t dst = stb + tl * 8192;
            #pragma unroll
            for (int h = 0; h < 2; h++) {
                int row = lrow + h * 64;
                cpa16(dst + row * 64 + ((lc ^ ((row >> 1) & 3)) << 4),
                      gp[tl] + (size_t)row * R + rof);
            }
        }
        asm volatile("cp.async.commit_group;" ::: "memory");
    }

    for (int ch = 0; ch < NC; ch++) {
        asm volatile("cp.async.wait_group 2;" ::: "memory");
        __syncthreads();
        uint32_t stb = sb + (ch % NSTAGE) * STG;

        #pragma unroll
        for (int kh = 0; kh < 2; kh++) {
            int kc = kh * 2;
            uint32_t ah[2][4], al[2][4], bh[8][2];
            #pragma unroll
            for (int mt = 0; mt < 2; mt++) {
                int row = wm * 32 + mt * 16 + aRow;
                uint32_t ad = stb + row * 64 + (((kc + aKg) ^ ((row >> 1) & 3)) << 4);
                ldsm4(ah[mt], ad);
                if (TILES == 3) ldsm4(al[mt], ad + 16384);
            }
            #pragma unroll
            for (int ng = 0; ng < 4; ng++) {
                int row = wn * 64 + ng * 16 + bRow;
                uint32_t bd = stb + 8192 + row * 64 + (((kc + bKg) ^ ((row >> 1) & 3)) << 4);
                uint32_t r4[4];
                ldsm4(r4, bd);
                bh[ng * 2][0] = r4[0]; bh[ng * 2][1] = r4[1];
                bh[ng * 2 + 1][0] = r4[2]; bh[ng * 2 + 1][1] = r4[3];
            }
            #pragma unroll
            for (int mt = 0; mt < 2; mt++)
                #pragma unroll
                for (int nt = 0; nt < 8; nt++) {
                    mma16816(acc[mt][nt], ah[mt], bh[nt]);
                    if (TILES == 3) mma16816(acc[mt][nt], al[mt], bh[nt]);
                }
        }

        int nx = ch + NSTAGE - 1;
        if (nx < NC) {
            uint32_t stb2 = sb + (nx % NSTAGE) * STG;
            size_t rof = (size_t)(nx * 32) + lc * 8;
            #pragma unroll
            for (int tl = 0; tl < TILES; tl++) {
                uint32_t dst = stb2 + tl * 8192;
                #pragma unroll
                for (int h = 0; h < 2; h++) {
                    int row = lrow + h * 64;
                    cpa16(dst + row * 64 + ((lc ^ ((row >> 1) & 3)) << 4),
                          gp[tl] + (size_t)row * R + rof);
                }
            }
        }
        asm volatile("cp.async.commit_group;" ::: "memory");
    }

    // epilogue
    int er = lane >> 2, ec = (lane & 3) * 2;
    #pragma unroll
    for (int mt = 0; mt < 2; mt++) {
        int obase = o0 + wm * 32 + mt * 16 + er;
        #pragma unroll
        for (int h = 0; h < 2; h++) {
            int o = obase + h * 8;
            if (o < Olim) {
                float bv = (bias != nullptr) ? bias[o] : 0.0f;
                size_t rb = (size_t)o * o_stride + (size_t)t * t_stride + p0 + wn * 64 + ec;
                #pragma unroll
                for (int nt = 0; nt < 8; nt++) {
                    float2* dp = (float2*)(outp + rb + nt * 8);
                    float2 wv;
                    wv.x = acc[mt][nt][h * 2 + 0] + bv;
                    wv.y = acc[mt][nt][h * 2 + 1] + bv;
                    *dp = wv;
                }
            }
        }
    }
}

// ---------------- launch ----------------
extern "C" void kernel_launch(void* const* d_in, const int* in_sizes, int n_in,
                              void* d_out, int out_size) {
    (void)in_sizes; (void)n_in; (void)out_size;
    const float* x      = (const float*)d_in[0];
    const float* w_off  = (const float*)d_in[1];
    const float* w_def  = (const float*)d_in[2];
    const float* w_temp = (const float*)d_in[3];
    const float* b_temp = (const float*)d_in[4];
    float* out = (float*)d_out;

    fp16 *B5p, *Bfp, *wofh, *wfh, *wfl;
    float* offp;
    cudaGetSymbolAddress((void**)&B5p,  g_B5);
    cudaGetSymbolAddress((void**)&Bfp,  g_Bf);
    cudaGetSymbolAddress((void**)&wofh, g_Woff_h);
    cudaGetSymbolAddress((void**)&wfh,  g_Wf_h);
    cudaGetSymbolAddress((void**)&wfl,  g_Wf_l);
    cudaGetSymbolAddress((void**)&offp, g_off);

    cudaFuncSetAttribute(gemm_mma<2>, cudaFuncAttributeMaxDynamicSharedMemorySize,
                         NSTAGE * 2 * 8192);
    cudaFuncSetAttribute(gemm_mma<3>, cudaFuncAttributeMaxDynamicSharedMemorySize,
                         NSTAGE * 3 * 8192);

    // weight splits
    splitw_off<<<dim3(256, 25), 256>>>(w_off, wofh);
    splitw_f  <<<dim3(256, 52), 256>>>(w_def, w_temp, wfh, wfl);

    // temporal im2col (independent of offset path) -> fused B, cols [6400, 13312)
    im2col3_k<<<dim3(TT, 72, 32), 256>>>(x, Bfp);

    // offset conv: im2col5 -> B5, 1-pass GEMM -> g_off
    im2col5_k<<<dim3(TT, 72, 32), 256>>>(x, B5p);
    gemm_mma<2><<<dim3(18, TT, 2), 256, NSTAGE * 2 * 8192>>>(
        wofh, nullptr, B5p, offp, R5, OFFC, PP, (long long)OFFC * PP, nullptr);

    // bilinear sampling -> fused B, cols [0, 6400)
    sample_k<<<dim3(TT, 72, 32), 256>>>(x, offp, Bfp);

    // fused deform + temporal 2-pass GEMM (bias folded in)
    gemm_mma<3><<<dim3(18, TT, 2), 256, NSTAGE * 3 * 8192>>>(
        wfh, wfl, Bfp, out, RF, 256, (long long)TT * PP, PP, b_temp);
}

// round 7
// speedup vs baseline: 4.9373x; 1.1878x over previous
#include <cuda_runtime.h>
#include <cuda_fp16.h>
#include <cstdint>

#define TT   4
#define HH   48
#define WWD  48
#define PP   2304          // 48*48
#define R5   6400          // 256*25
#define R3   6912          // 256*27
#define RF   13312         // R5 + R3 fused K
#define OFFC 200           // 4*2*25

typedef __half fp16;

// ---------------- scratch (static device globals; no allocation) ----------------
__device__ fp16 g_B5[(size_t)TT * PP * R5];   // [t][p][r5]   im2col5 of x (offset conv B)
__device__ fp16 g_Bf[(size_t)TT * PP * RF];   // [t][p][rf]   sampler(0..6400) + im2col3(6400..)
__device__ fp16 g_Woff_h[256 * R5];
__device__ fp16 g_Wf_h[256 * RF];
__device__ float g_off[TT * OFFC * PP];       // [t][och][p]

// ---------------- helpers ----------------
__device__ __forceinline__ uint32_t smem_u32(const void* p) {
    uint32_t a;
    asm("{ .reg .u64 t; cvta.to.shared.u64 t, %1; cvt.u32.u64 %0, t; }" : "=r"(a) : "l"(p));
    return a;
}
__device__ __forceinline__ void cpa16(uint32_t dst, const void* src) {
    asm volatile("cp.async.cg.shared.global [%0], [%1], 16;" :: "r"(dst), "l"(src) : "memory");
}
__device__ __forceinline__ void ldsm4(uint32_t* r, uint32_t a) {
    asm volatile("ldmatrix.sync.aligned.m8n8.x4.shared.b16 {%0,%1,%2,%3}, [%4];"
                 : "=r"(r[0]), "=r"(r[1]), "=r"(r[2]), "=r"(r[3]) : "r"(a));
}
__device__ __forceinline__ void mma16816(float* c, const uint32_t* a, const uint32_t* b) {
    asm volatile("mma.sync.aligned.m16n8k16.row.col.f32.f16.f16.f32 "
                 "{%0,%1,%2,%3}, {%4,%5,%6,%7}, {%8,%9}, {%0,%1,%2,%3};"
                 : "+f"(c[0]), "+f"(c[1]), "+f"(c[2]), "+f"(c[3])
                 : "r"(a[0]), "r"(a[1]), "r"(a[2]), "r"(a[3]), "r"(b[0]), "r"(b[1]));
}

// ---------------- weight pack (offset conv): fp16, pad O to 256 ----------------
__global__ void packw_off(const float* __restrict__ src, fp16* __restrict__ h) {
    int o = blockIdx.x;
    int r = blockIdx.y * 256 + threadIdx.x;
    float v = (o < OFFC) ? src[(size_t)o * R5 + r] : 0.0f;
    h[(size_t)o * R5 + r] = __float2half_rn(v);
}

// ---------------- weight pack (fused): [w_def | w_temp] fp16 over RF ----------------
__global__ void packw_f(const float* __restrict__ wdef, const float* __restrict__ wtmp,
                        fp16* __restrict__ h) {
    int o = blockIdx.x;
    int r = blockIdx.y * 256 + threadIdx.x;
    float v = (r < R5) ? wdef[(size_t)o * R5 + r] : wtmp[(size_t)o * R3 + (r - R5)];
    h[(size_t)o * RF + r] = __float2half_rn(v);
}

// ---------------- im2col 1x5x5 pad2 -> B5[t][p][r5] fp16 ----------------
__global__ void __launch_bounds__(256) im2col5_k(const float* __restrict__ x,
                                                 fp16* __restrict__ B) {
    __shared__ float st[32][201];
    int t = blockIdx.x, p0 = blockIdx.y * 32, c0 = blockIdx.z * 8;
    int lane = threadIdx.x & 31, w = threadIdx.x >> 5;
    int c = c0 + w;
    int p = p0 + lane, py = p / WWD, px = p % WWD;
    const float* xs = x + ((size_t)c * TT + t) * PP;
    #pragma unroll
    for (int k = 0; k < 25; k++) {
        int y = py + k / 5 - 2, xx = px + k % 5 - 2;
        float v = (y >= 0 && y < HH && xx >= 0 && xx < WWD) ? xs[y * WWD + xx] : 0.0f;
        st[lane][w * 25 + k] = v;
    }
    __syncthreads();
    #pragma unroll
    for (int rr = 0; rr < 4; rr++) {
        int row = w * 4 + rr;
        size_t base = (size_t)(t * PP + p0 + row) * R5 + c0 * 25;
        #pragma unroll
        for (int j = lane * 2; j < 200; j += 64)
            *(__half2*)(B + base + j) = __floats2half2_rn(st[row][j], st[row][j + 1]);
    }
}

// ---------------- im2col 3x3x3 pad1 -> Bf[t][p][6400 + r3] fp16 ----------------
__global__ void __launch_bounds__(256) im2col3_k(const float* __restrict__ x,
                                                 fp16* __restrict__ B) {
    __shared__ float st[32][217];
    int t = blockIdx.x, p0 = blockIdx.y * 32, c0 = blockIdx.z * 8;
    int lane = threadIdx.x & 31, w = threadIdx.x >> 5;
    int c = c0 + w;
    int p = p0 + lane, py = p / WWD, px = p % WWD;
    const float* xc = x + (size_t)c * TT * PP;
    #pragma unroll
    for (int q = 0; q < 27; q++) {
        int kt = q / 9 - 1, rq = q % 9, ky = rq / 3 - 1, kx = rq % 3 - 1;
        int tt = t + kt, y = py + ky, xx = px + kx;
        float v = 0.0f;
        if (tt >= 0 && tt < TT && y >= 0 && y < HH && xx >= 0 && xx < WWD)
            v = xc[(size_t)tt * PP + y * WWD + xx];
        st[lane][w * 27 + q] = v;
    }
    __syncthreads();
    #pragma unroll
    for (int rr = 0; rr < 4; rr++) {
        int row = w * 4 + rr;
        size_t base = (size_t)(t * PP + p0 + row) * RF + R5 + c0 * 27;
        #pragma unroll
        for (int j = lane * 2; j < 216; j += 64)
            *(__half2*)(B + base + j) = __floats2half2_rn(st[row][j], st[row][j + 1]);
    }
}

// ---------------- bilinear sampler -> Bf[t][p][r5] fp16 ----------------
__global__ void __launch_bounds__(256) sample_k(const float* __restrict__ x,
                                                const float* __restrict__ off,
                                                fp16* __restrict__ B) {
    __shared__ float st[32][201];
    int t = blockIdx.x, p0 = blockIdx.y * 32;
    int dg = blockIdx.z >> 3;
    int c0 = dg * 64 + (blockIdx.z & 7) * 8;
    int lane = threadIdx.x & 31, w = threadIdx.x >> 5;
    int c = c0 + w;
    int p = p0 + lane, py = p / WWD, px = p % WWD;
    const float* xc = x + ((size_t)c * TT + t) * PP;
    #pragma unroll
    for (int k = 0; k < 25; k++) {
        int ky = k / 5 - 2, kx = k % 5 - 2;
        const float* offy = off + ((size_t)t * OFFC + (dg * 25 + k) * 2) * PP;
        float sy = (float)(py + ky) + offy[p];
        float sx = (float)(px + kx) + offy[PP + p];
        float fy = floorf(sy), fx = floorf(sx);
        int y0 = (int)fy, x0 = (int)fx;
        float wy = sy - fy, wx = sx - fx;
        int y1 = y0 + 1, x1 = x0 + 1;
        float vy0 = (y0 >= 0 && y0 < HH) ? 1.0f : 0.0f;
        float vy1 = (y1 >= 0 && y1 < HH) ? 1.0f : 0.0f;
        float vx0 = (x0 >= 0 && x0 < WWD) ? 1.0f : 0.0f;
        float vx1 = (x1 >= 0 && x1 < WWD) ? 1.0f : 0.0f;
        int y0c = min(max(y0, 0), HH - 1), y1c = min(max(y1, 0), HH - 1);
        int x0c = min(max(x0, 0), WWD - 1), x1c = min(max(x1, 0), WWD - 1);
        float w00 = (1.0f - wy) * (1.0f - wx) * vy0 * vx0;
        float w01 = (1.0f - wy) * wx          * vy0 * vx1;
        float w10 = wy          * (1.0f - wx) * vy1 * vx0;
        float w11 = wy          * wx          * vy1 * vx1;
        float v = w00 * xc[y0c * WWD + x0c] + w01 * xc[y0c * WWD + x1c] +
                  w10 * xc[y1c * WWD + x0c] + w11 * xc[y1c * WWD + x1c];
        st[lane][w * 25 + k] = v;
    }
    __syncthreads();
    #pragma unroll
    for (int rr = 0; rr < 4; rr++) {
        int row = w * 4 + rr;
        size_t base = (size_t)(t * PP + p0 + row) * RF + c0 * 25;
        #pragma unroll
        for (int j = lane * 2; j < 200; j += 64)
            *(__half2*)(B + base + j) = __floats2half2_rn(st[row][j], st[row][j + 1]);
    }
}

// ---------------- 1-pass fp16 mma.sync GEMM ----------------
// Tile 128(o) x 128(p), K chunk 32, 4 stages. Warp grid 4(m) x 2(n): warp tile 32x64.
// Stage layout: A @0, B @8192. XOR swizzle, conflict-free.
#define NSTAGE 4
#define STG    16384
#define GSMEM  (NSTAGE * STG)

__global__ void __launch_bounds__(256, 1) gemm_mma(
    const fp16* __restrict__ Wh, const fp16* __restrict__ Bh,
    float* __restrict__ outp, int R, int Olim,
    long long o_stride, long long t_stride,
    const float* __restrict__ bias)
{
    extern __shared__ char smraw[];
    uint32_t sb = smem_u32(smraw);
    int tid = threadIdx.x, lane = tid & 31, wid = tid >> 5;
    int wm = wid & 3, wn = wid >> 2;               // 4 x 2 warp grid -> 32x64 per warp
    int p0 = blockIdx.x * 128, t = blockIdx.y, o0 = blockIdx.z * 128;

    const fp16* gp[2];
    gp[0] = Wh + (size_t)o0 * R;
    gp[1] = Bh + ((size_t)t * PP + p0) * R;

    int lrow = tid >> 2;           // 0..63
    int lc   = tid & 3;            // 16B chunk within 64B row
    int NC = R >> 5;

    int aRow = (lane & 7) + ((lane >> 3) & 1) * 8;  // A: within m16 tile
    int aKg  = (lane >> 4) & 1;
    int bRow = (lane & 7) + ((lane >> 4) & 1) * 8;  // B: within n16 (2 tiles)
    int bKg  = (lane >> 3) & 1;

    float acc[2][8][4];
    #pragma unroll
    for (int i = 0; i < 2; i++)
        #pragma unroll
        for (int j = 0; j < 8; j++)
            #pragma unroll
            for (int q = 0; q < 4; q++) acc[i][j][q] = 0.0f;

    // prologue: load chunks 0..NSTAGE-2
    #pragma unroll
    for (int pc = 0; pc < NSTAGE - 1; pc++) {
        uint32_t stb = sb + pc * STG;
        size_t rof = (size_t)(pc * 32) + lc * 8;
        #pragma unroll
        for (int tl = 0; tl < 2; tl++) {
            uint32_t dst = stb + tl * 8192;
            #pragma unroll
            for (int h = 0; h < 2; h++) {
                int row = lrow + h * 64;
                cpa16(dst + row * 64 + ((lc ^ ((row >> 1) & 3)) << 4),
                      gp[tl] + (size_t)row * R + rof);
            }
        }
        asm volatile("cp.async.commit_group;" ::: "memory");
    }

    for (int ch = 0; ch < NC; ch++) {
        asm volatile("cp.async.wait_group 2;" ::: "memory");
        __syncthreads();
        uint32_t stb = sb + (ch % NSTAGE) * STG;

        #pragma unroll
        for (int kh = 0; kh < 2; kh++) {
            int kc = kh * 2;
            uint32_t ah[2][4], bh[8][2];
            #pragma unroll
            for (int mt = 0; mt < 2; mt++) {
                int row = wm * 32 + mt * 16 + aRow;
                uint32_t ad = stb + row * 64 + (((kc + aKg) ^ ((row >> 1) & 3)) << 4);
                ldsm4(ah[mt], ad);
            }
            #pragma unroll
            for (int ng = 0; ng < 4; ng++) {
                int row = wn * 64 + ng * 16 + bRow;
                uint32_t bd = stb + 8192 + row * 64 + (((kc + bKg) ^ ((row >> 1) & 3)) << 4);
                uint32_t r4[4];
                ldsm4(r4, bd);
                bh[ng * 2][0] = r4[0]; bh[ng * 2][1] = r4[1];
                bh[ng * 2 + 1][0] = r4[2]; bh[ng * 2 + 1][1] = r4[3];
            }
            #pragma unroll
            for (int mt = 0; mt < 2; mt++)
                #pragma unroll
                for (int nt = 0; nt < 8; nt++)
                    mma16816(acc[mt][nt], ah[mt], bh[nt]);
        }

        int nx = ch + NSTAGE - 1;
        if (nx < NC) {
            uint32_t stb2 = sb + (nx % NSTAGE) * STG;
            size_t rof = (size_t)(nx * 32) + lc * 8;
            #pragma unroll
            for (int tl = 0; tl < 2; tl++) {
                uint32_t dst = stb2 + tl * 8192;
                #pragma unroll
                for (int h = 0; h < 2; h++) {
                    int row = lrow + h * 64;
                    cpa16(dst + row * 64 + ((lc ^ ((row >> 1) & 3)) << 4),
                          gp[tl] + (size_t)row * R + rof);
                }
            }
        }
        asm volatile("cp.async.commit_group;" ::: "memory");
    }

    // epilogue
    int er = lane >> 2, ec = (lane & 3) * 2;
    #pragma unroll
    for (int mt = 0; mt < 2; mt++) {
        int obase = o0 + wm * 32 + mt * 16 + er;
        #pragma unroll
        for (int h = 0; h < 2; h++) {
            int o = obase + h * 8;
            if (o < Olim) {
                float bv = (bias != nullptr) ? bias[o] : 0.0f;
                size_t rb = (size_t)o * o_stride + (size_t)t * t_stride + p0 + wn * 64 + ec;
                #pragma unroll
                for (int nt = 0; nt < 8; nt++) {
                    float2* dp = (float2*)(outp + rb + nt * 8);
                    float2 wv;
                    wv.x = acc[mt][nt][h * 2 + 0] + bv;
                    wv.y = acc[mt][nt][h * 2 + 1] + bv;
                    *dp = wv;
                }
            }
        }
    }
}

// ---------------- launch ----------------
extern "C" void kernel_launch(void* const* d_in, const int* in_sizes, int n_in,
                              void* d_out, int out_size) {
    (void)in_sizes; (void)n_in; (void)out_size;
    const float* x      = (const float*)d_in[0];
    const float* w_off  = (const float*)d_in[1];
    const float* w_def  = (const float*)d_in[2];
    const float* w_temp = (const float*)d_in[3];
    const float* b_temp = (const float*)d_in[4];
    float* out = (float*)d_out;

    fp16 *B5p, *Bfp, *wofh, *wfh;
    float* offp;
    cudaGetSymbolAddress((void**)&B5p,  g_B5);
    cudaGetSymbolAddress((void**)&Bfp,  g_Bf);
    cudaGetSymbolAddress((void**)&wofh, g_Woff_h);
    cudaGetSymbolAddress((void**)&wfh,  g_Wf_h);
    cudaGetSymbolAddress((void**)&offp, g_off);

    cudaFuncSetAttribute(gemm_mma, cudaFuncAttributeMaxDynamicSharedMemorySize, GSMEM);

    // weight packs
    packw_off<<<dim3(256, 25), 256>>>(w_off, wofh);
    packw_f  <<<dim3(256, 52), 256>>>(w_def, w_temp, wfh);

    // temporal im2col (independent of offset path) -> fused B, cols [6400, 13312)
    im2col3_k<<<dim3(TT, 72, 32), 256>>>(x, Bfp);

    // offset conv: im2col5 -> B5, GEMM -> g_off
    im2col5_k<<<dim3(TT, 72, 32), 256>>>(x, B5p);
    gemm_mma<<<dim3(18, TT, 2), 256, GSMEM>>>(
        wofh, B5p, offp, R5, OFFC, PP, (long long)OFFC * PP, nullptr);

    // bilinear sampling -> fused B, cols [0, 6400)
    sample_k<<<dim3(TT, 72, 32), 256>>>(x, offp, Bfp);

    // fused deform + temporal GEMM (bias folded in)
    gemm_mma<<<dim3(18, TT, 2), 256, GSMEM>>>(
        wfh, Bfp, out, RF, 256, (long long)TT * PP, PP, b_temp);
}

// round 8
// speedup vs baseline: 5.3536x; 1.0843x over previous
#include <cuda_runtime.h>
#include <cuda_fp16.h>
#include <cstdint>

#define TT   4
#define HH   48
#define WWD  48
#define PP   2304          // 48*48
#define R5   6400          // 256*25
#define R3   6912          // 256*27
#define RF   13312         // R5 + R3 fused K
#define OFFC 200           // 4*2*25

typedef __half fp16;

// ---------------- scratch (static device globals; no allocation) ----------------
__device__ fp16 g_B5[(size_t)TT * PP * R5];   // [t][p][r5]   im2col5 of x (offset conv B)
__device__ fp16 g_Bf[(size_t)TT * PP * RF];   // [t][p][rf]   sampler(0..6400) + im2col3(6400..)
__device__ fp16 g_Woff_h[256 * R5];
__device__ fp16 g_Wf_h[256 * RF];
__device__ float g_off[TT * OFFC * PP];       // [t][och][p]

// ---------------- side stream for fork-join overlap (created at load, never freed) ----------------
static cudaStream_t g_side;
static cudaEvent_t g_fork, g_join;
struct _StreamInit {
    _StreamInit() {
        cudaStreamCreateWithFlags(&g_side, cudaStreamNonBlocking);
        cudaEventCreateWithFlags(&g_fork, cudaEventDisableTiming);
        cudaEventCreateWithFlags(&g_join, cudaEventDisableTiming);
    }
};
static _StreamInit _si;

// ---------------- helpers ----------------
__device__ __forceinline__ uint32_t smem_u32(const void* p) {
    uint32_t a;
    asm("{ .reg .u64 t; cvta.to.shared.u64 t, %1; cvt.u32.u64 %0, t; }" : "=r"(a) : "l"(p));
    return a;
}
__device__ __forceinline__ void cpa16(uint32_t dst, const void* src) {
    asm volatile("cp.async.cg.shared.global [%0], [%1], 16;" :: "r"(dst), "l"(src) : "memory");
}
__device__ __forceinline__ void ldsm4(uint32_t* r, uint32_t a) {
    asm volatile("ldmatrix.sync.aligned.m8n8.x4.shared.b16 {%0,%1,%2,%3}, [%4];"
                 : "=r"(r[0]), "=r"(r[1]), "=r"(r[2]), "=r"(r[3]) : "r"(a));
}
__device__ __forceinline__ void mma16816(float* c, const uint32_t* a, const uint32_t* b) {
    asm volatile("mma.sync.aligned.m16n8k16.row.col.f32.f16.f16.f32 "
                 "{%0,%1,%2,%3}, {%4,%5,%6,%7}, {%8,%9}, {%0,%1,%2,%3};"
                 : "+f"(c[0]), "+f"(c[1]), "+f"(c[2]), "+f"(c[3])
                 : "r"(a[0]), "r"(a[1]), "r"(a[2]), "r"(a[3]), "r"(b[0]), "r"(b[1]));
}

// ---------------- weight pack (offset conv): fp16, pad O to 256 ----------------
__global__ void packw_off(const float* __restrict__ src, fp16* __restrict__ h) {
    int o = blockIdx.x;
    int r = blockIdx.y * 256 + threadIdx.x;
    float v = (o < OFFC) ? src[(size_t)o * R5 + r] : 0.0f;
    h[(size_t)o * R5 + r] = __float2half_rn(v);
}

// ---------------- weight pack (fused): [w_def | w_temp] fp16 over RF ----------------
__global__ void packw_f(const float* __restrict__ wdef, const float* __restrict__ wtmp,
                        fp16* __restrict__ h) {
    int o = blockIdx.x;
    int r = blockIdx.y * 256 + threadIdx.x;
    float v = (r < R5) ? wdef[(size_t)o * R5 + r] : wtmp[(size_t)o * R3 + (r - R5)];
    h[(size_t)o * RF + r] = __float2half_rn(v);
}

// ---------------- im2col 1x5x5 pad2 -> B5[t][p][r5] fp16 ----------------
__global__ void __launch_bounds__(256) im2col5_k(const float* __restrict__ x,
                                                 fp16* __restrict__ B) {
    __shared__ float st[32][201];
    int t = blockIdx.x, p0 = blockIdx.y * 32, c0 = blockIdx.z * 8;
    int lane = threadIdx.x & 31, w = threadIdx.x >> 5;
    int c = c0 + w;
    int p = p0 + lane, py = p / WWD, px = p % WWD;
    const float* xs = x + ((size_t)c * TT + t) * PP;
    #pragma unroll
    for (int k = 0; k < 25; k++) {
        int y = py + k / 5 - 2, xx = px + k % 5 - 2;
        float v = (y >= 0 && y < HH && xx >= 0 && xx < WWD) ? xs[y * WWD + xx] : 0.0f;
        st[lane][w * 25 + k] = v;
    }
    __syncthreads();
    #pragma unroll
    for (int rr = 0; rr < 4; rr++) {
        int row = w * 4 + rr;
        size_t base = (size_t)(t * PP + p0 + row) * R5 + c0 * 25;
        #pragma unroll
        for (int j = lane * 2; j < 200; j += 64)
            *(__half2*)(B + base + j) = __floats2half2_rn(st[row][j], st[row][j + 1]);
    }
}

// ---------------- im2col 3x3x3 pad1 -> Bf[t][p][6400 + r3] fp16 ----------------
__global__ void __launch_bounds__(256) im2col3_k(const float* __restrict__ x,
                                                 fp16* __restrict__ B) {
    __shared__ float st[32][217];
    int t = blockIdx.x, p0 = blockIdx.y * 32, c0 = blockIdx.z * 8;
    int lane = threadIdx.x & 31, w = threadIdx.x >> 5;
    int c = c0 + w;
    int p = p0 + lane, py = p / WWD, px = p % WWD;
    const float* xc = x + (size_t)c * TT * PP;
    #pragma unroll
    for (int q = 0; q < 27; q++) {
        int kt = q / 9 - 1, rq = q % 9, ky = rq / 3 - 1, kx = rq % 3 - 1;
        int tt = t + kt, y = py + ky, xx = px + kx;
        float v = 0.0f;
        if (tt >= 0 && tt < TT && y >= 0 && y < HH && xx >= 0 && xx < WWD)
            v = xc[(size_t)tt * PP + y * WWD + xx];
        st[lane][w * 27 + q] = v;
    }
    __syncthreads();
    #pragma unroll
    for (int rr = 0; rr < 4; rr++) {
        int row = w * 4 + rr;
        size_t base = (size_t)(t * PP + p0 + row) * RF + R5 + c0 * 27;
        #pragma unroll
        for (int j = lane * 2; j < 216; j += 64)
            *(__half2*)(B + base + j) = __floats2half2_rn(st[row][j], st[row][j + 1]);
    }
}

// ---------------- bilinear sampler -> Bf[t][p][r5] fp16 ----------------
__global__ void __launch_bounds__(256) sample_k(const float* __restrict__ x,
                                                const float* __restrict__ off,
                                                fp16* __restrict__ B) {
    __shared__ float st[32][201];
    int t = blockIdx.x, p0 = blockIdx.y * 32;
    int dg = blockIdx.z >> 3;
    int c0 = dg * 64 + (blockIdx.z & 7) * 8;
    int lane = threadIdx.x & 31, w = threadIdx.x >> 5;
    int c = c0 + w;
    int p = p0 + lane, py = p / WWD, px = p % WWD;
    const float* xc = x + ((size_t)c * TT + t) * PP;
    #pragma unroll
    for (int k = 0; k < 25; k++) {
        int ky = k / 5 - 2, kx = k % 5 - 2;
        const float* offy = off + ((size_t)t * OFFC + (dg * 25 + k) * 2) * PP;
        float sy = (float)(py + ky) + offy[p];
        float sx = (float)(px + kx) + offy[PP + p];
        float fy = floorf(sy), fx = floorf(sx);
        int y0 = (int)fy, x0 = (int)fx;
        float wy = sy - fy, wx = sx - fx;
        int y1 = y0 + 1, x1 = x0 + 1;
        float vy0 = (y0 >= 0 && y0 < HH) ? 1.0f : 0.0f;
        float vy1 = (y1 >= 0 && y1 < HH) ? 1.0f : 0.0f;
        float vx0 = (x0 >= 0 && x0 < WWD) ? 1.0f : 0.0f;
        float vx1 = (x1 >= 0 && x1 < WWD) ? 1.0f : 0.0f;
        int y0c = min(max(y0, 0), HH - 1), y1c = min(max(y1, 0), HH - 1);
        int x0c = min(max(x0, 0), WWD - 1), x1c = min(max(x1, 0), WWD - 1);
        float w00 = (1.0f - wy) * (1.0f - wx) * vy0 * vx0;
        float w01 = (1.0f - wy) * wx          * vy0 * vx1;
        float w10 = wy          * (1.0f - wx) * vy1 * vx0;
        float w11 = wy          * wx          * vy1 * vx1;
        float v = w00 * xc[y0c * WWD + x0c] + w01 * xc[y0c * WWD + x1c] +
                  w10 * xc[y1c * WWD + x0c] + w11 * xc[y1c * WWD + x1c];
        st[lane][w * 25 + k] = v;
    }
    __syncthreads();
    #pragma unroll
    for (int rr = 0; rr < 4; rr++) {
        int row = w * 4 + rr;
        size_t base = (size_t)(t * PP + p0 + row) * RF + c0 * 25;
        #pragma unroll
        for (int j = lane * 2; j < 200; j += 64)
            *(__half2*)(B + base + j) = __floats2half2_rn(st[row][j], st[row][j + 1]);
    }
}

// ---------------- 1-pass fp16 mma.sync GEMM, K chunk 64 ----------------
// Tile 128(o) x 128(p), K chunk 64 (128B smem rows), 3 stages (96 KB).
// Warp grid 4(m) x 2(n): warp tile 32x64. Swizzle: 16B col ^ (row & 7).
#define NSTAGE 3
#define STG    32768
#define GSMEM  (NSTAGE * STG)

__global__ void __launch_bounds__(256, 1) gemm_mma(
    const fp16* __restrict__ Wh, const fp16* __restrict__ Bh,
    float* __restrict__ outp, int R, int Olim,
    long long o_stride, long long t_stride,
    const float* __restrict__ bias)
{
    extern __shared__ char smraw[];
    uint32_t sb = smem_u32(smraw);
    int tid = threadIdx.x, lane = tid & 31, wid = tid >> 5;
    int wm = wid & 3, wn = wid >> 2;               // 4 x 2 warp grid -> 32x64 per warp
    int p0 = blockIdx.x * 128, t = blockIdx.y, o0 = blockIdx.z * 128;

    const fp16* gp[2];
    gp[0] = Wh + (size_t)o0 * R;
    gp[1] = Bh + ((size_t)t * PP + p0) * R;

    int c8 = tid & 7;              // 16B col (0..7) within 128B row
    int rb = tid >> 3;             // 0..31
    int NC = R >> 6;

    int aRow = (lane & 7) + ((lane >> 3) & 1) * 8;  // A: row within m16 tile
    int aKg  = (lane >> 4) & 1;                     // k8 half
    int bRow = (lane & 7) + ((lane >> 4) & 1) * 8;  // B: row within n16
    int bKg  = (lane >> 3) & 1;

    float acc[2][8][4];
    #pragma unroll
    for (int i = 0; i < 2; i++)
        #pragma unroll
        for (int j = 0; j < 8; j++)
            #pragma unroll
            for (int q = 0; q < 4; q++) acc[i][j][q] = 0.0f;

    // prologue: load chunks 0,1
    #pragma unroll
    for (int pc = 0; pc < 2; pc++) {
        uint32_t stb = sb + pc * STG;
        size_t rof = (size_t)(pc * 64) + c8 * 8;
        #pragma unroll
        for (int tl = 0; tl < 2; tl++) {
            uint32_t dst = stb + tl * 16384;
            #pragma unroll
            for (int j = 0; j < 4; j++) {
                int row = rb + 32 * j;
                cpa16(dst + row * 128 + ((c8 ^ (row & 7)) << 4),
                      gp[tl] + (size_t)row * R + rof);
            }
        }
        asm volatile("cp.async.commit_group;" ::: "memory");
    }

    for (int ch = 0; ch < NC; ch++) {
        asm volatile("cp.async.wait_group 1;" ::: "memory");
        __syncthreads();
        uint32_t stb = sb + (ch % NSTAGE) * STG;

        #pragma unroll
        for (int kk = 0; kk < 4; kk++) {
            uint32_t ah[2][4], bh[8][2];
            #pragma unroll
            for (int mt = 0; mt < 2; mt++) {
                int row = wm * 32 + mt * 16 + aRow;
                uint32_t ad = stb + row * 128 + (((kk * 2 + aKg) ^ (row & 7)) << 4);
                ldsm4(ah[mt], ad);
            }
            #pragma unroll
            for (int ng = 0; ng < 4; ng++) {
                int row = wn * 64 + ng * 16 + bRow;
                uint32_t bd = stb + 16384 + row * 128 + (((kk * 2 + bKg) ^ (row & 7)) << 4);
                uint32_t r4[4];
                ldsm4(r4, bd);
                bh[ng * 2][0] = r4[0]; bh[ng * 2][1] = r4[1];
                bh[ng * 2 + 1][0] = r4[2]; bh[ng * 2 + 1][1] = r4[3];
            }
            #pragma unroll
            for (int mt = 0; mt < 2; mt++)
                #pragma unroll
                for (int nt = 0; nt < 8; nt++)
                    mma16816(acc[mt][nt], ah[mt], bh[nt]);
        }

        int nx = ch + 2;
        if (nx < NC) {
            uint32_t stb2 = sb + (nx % NSTAGE) * STG;
            size_t rof = (size_t)(nx * 64) + c8 * 8;
            #pragma unroll
            for (int tl = 0; tl < 2; tl++) {
                uint32_t dst = stb2 + tl * 16384;
                #pragma unroll
                for (int j = 0; j < 4; j++) {
                    int row = rb + 32 * j;
                    cpa16(dst + row * 128 + ((c8 ^ (row & 7)) << 4),
                          gp[tl] + (size_t)row * R + rof);
                }
            }
        }
        asm volatile("cp.async.commit_group;" ::: "memory");
    }

    // epilogue
    int er = lane >> 2, ec = (lane & 3) * 2;
    #pragma unroll
    for (int mt = 0; mt < 2; mt++) {
        int obase = o0 + wm * 32 + mt * 16 + er;
        #pragma unroll
        for (int h = 0; h < 2; h++) {
            int o = obase + h * 8;
            if (o < Olim) {
                float bv = (bias != nullptr) ? bias[o] : 0.0f;
                size_t rb2 = (size_t)o * o_stride + (size_t)t * t_stride + p0 + wn * 64 + ec;
                #pragma unroll
                for (int nt = 0; nt < 8; nt++) {
                    float2* dp = (float2*)(outp + rb2 + nt * 8);
                    float2 wv;
                    wv.x = acc[mt][nt][h * 2 + 0] + bv;
                    wv.y = acc[mt][nt][h * 2 + 1] + bv;
                    *dp = wv;
                }
            }
        }
    }
}

// ---------------- launch ----------------
extern "C" void kernel_launch(void* const* d_in, const int* in_sizes, int n_in,
                              void* d_out, int out_size) {
    (void)in_sizes; (void)n_in; (void)out_size;
    const float* x      = (const float*)d_in[0];
    const float* w_off  = (const float*)d_in[1];
    const float* w_def  = (const float*)d_in[2];
    const float* w_temp = (const float*)d_in[3];
    const float* b_temp = (const float*)d_in[4];
    float* out = (float*)d_out;

    fp16 *B5p, *Bfp, *wofh, *wfh;
    float* offp;
    cudaGetSymbolAddress((void**)&B5p,  g_B5);
    cudaGetSymbolAddress((void**)&Bfp,  g_Bf);
    cudaGetSymbolAddress((void**)&wofh, g_Woff_h);
    cudaGetSymbolAddress((void**)&wfh,  g_Wf_h);
    cudaGetSymbolAddress((void**)&offp, g_off);

    cudaFuncSetAttribute(gemm_mma, cudaFuncAttributeMaxDynamicSharedMemorySize, GSMEM);

    // fork: side stream does the fused-GEMM-only prep (im2col3 + packw_f)
    cudaEventRecord(g_fork, 0);
    cudaStreamWaitEvent(g_side, g_fork, 0);
    im2col3_k<<<dim3(TT, 72, 32), 256, 0, g_side>>>(x, Bfp);
    packw_f<<<dim3(256, 52), 256, 0, g_side>>>(w_def, w_temp, wfh);
    cudaEventRecord(g_join, g_side);

    // main stream: offset path
    packw_off<<<dim3(256, 25), 256>>>(w_off, wofh);
    im2col5_k<<<dim3(TT, 72, 32), 256>>>(x, B5p);
    gemm_mma<<<dim3(18, TT, 2), 256, GSMEM>>>(
        wofh, B5p, offp, R5, OFFC, PP, (long long)OFFC * PP, nullptr);

    // bilinear sampling -> fused B, cols [0, 6400)
    sample_k<<<dim3(TT, 72, 32), 256>>>(x, offp, Bfp);

    // join side stream, then fused deform + temporal GEMM (bias folded in)
    cudaStreamWaitEvent(0, g_join, 0);
    gemm_mma<<<dim3(18, TT, 2), 256, GSMEM>>>(
        wfh, Bfp, out, RF, 256, (long long)TT * PP, PP, b_temp);
}

// round 9
// speedup vs baseline: 7.3893x; 1.3803x over previous
#include <cuda_runtime.h>
#include <cuda_fp16.h>
#include <cstdint>

#define TT   4
#define HH   48
#define WWD  48
#define PP   2304          // 48*48
#define R5   6400          // 256*25
#define R3   6912          // 256*27
#define RF   13312         // R5 + R3 fused K
#define OFFC 200           // 4*2*25

typedef __half fp16;

// ---------------- scratch (static device globals; no allocation) ----------------
__device__ fp16 g_xT[(size_t)TT * PP * 256];  // [t][p][c] fp16 transpose of x (4.7 MB, L2-resident)
__device__ fp16 g_Bs[(size_t)TT * PP * R5];   // [t][p][k*256+c] sampled B (k-major)
__device__ fp16 g_Woff_h[256 * R5];           // [o][k*256+c]
__device__ fp16 g_Wf_h[256 * RF];             // [o][r] k-major both halves
__device__ float g_off[TT * OFFC * PP];       // [t][och][p]

// ---------------- side stream for fork-join overlap ----------------
static cudaStream_t g_side;
static cudaEvent_t g_fork, g_e1, g_e2;
struct _StreamInit {
    _StreamInit() {
        cudaStreamCreateWithFlags(&g_side, cudaStreamNonBlocking);
        cudaEventCreateWithFlags(&g_fork, cudaEventDisableTiming);
        cudaEventCreateWithFlags(&g_e1, cudaEventDisableTiming);
        cudaEventCreateWithFlags(&g_e2, cudaEventDisableTiming);
    }
};
static _StreamInit _si;

// ---------------- helpers ----------------
__device__ __forceinline__ uint32_t smem_u32(const void* p) {
    uint32_t a;
    asm("{ .reg .u64 t; cvta.to.shared.u64 t, %1; cvt.u32.u64 %0, t; }" : "=r"(a) : "l"(p));
    return a;
}
__device__ __forceinline__ void cpa16(uint32_t dst, const void* src) {
    asm volatile("cp.async.cg.shared.global [%0], [%1], 16;" :: "r"(dst), "l"(src) : "memory");
}
__device__ __forceinline__ void cpa16z(uint32_t dst, const void* src, int vld16) {
    // vld16 = 16 (copy) or 0 (zero-fill)
    asm volatile("cp.async.cg.shared.global [%0], [%1], 16, %2;"
                 :: "r"(dst), "l"(src), "r"(vld16) : "memory");
}
__device__ __forceinline__ void ldsm4(uint32_t* r, uint32_t a) {
    asm volatile("ldmatrix.sync.aligned.m8n8.x4.shared.b16 {%0,%1,%2,%3}, [%4];"
                 : "=r"(r[0]), "=r"(r[1]), "=r"(r[2]), "=r"(r[3]) : "r"(a));
}
__device__ __forceinline__ void mma16816(float* c, const uint32_t* a, const uint32_t* b) {
    asm volatile("mma.sync.aligned.m16n8k16.row.col.f32.f16.f16.f32 "
                 "{%0,%1,%2,%3}, {%4,%5,%6,%7}, {%8,%9}, {%0,%1,%2,%3};"
                 : "+f"(c[0]), "+f"(c[1]), "+f"(c[2]), "+f"(c[3])
                 : "r"(a[0]), "r"(a[1]), "r"(a[2]), "r"(a[3]), "r"(b[0]), "r"(b[1]));
}

// ---------------- x transpose: x[c][t][p] fp32 -> xT[t][p][c] fp16 ----------------
__global__ void __launch_bounds__(256) transpose_x(const float* __restrict__ x,
                                                   fp16* __restrict__ xT) {
    __shared__ float tl[32][33];
    int t = blockIdx.x, p0 = blockIdx.y * 32, c0 = blockIdx.z * 32;
    int tx = threadIdx.x & 31, ty = threadIdx.x >> 5;
    #pragma unroll
    for (int i = ty; i < 32; i += 8)
        tl[i][tx] = x[((size_t)(c0 + i) * TT + t) * PP + p0 + tx];
    __syncthreads();
    #pragma unroll
    for (int i = ty; i < 32; i += 8)
        xT[((size_t)t * PP + p0 + i) * 256 + c0 + tx] = __float2half_rn(tl[tx][i]);
}

// ---------------- weight pack (offset): w_off[o][c][k] -> [o][k*256+c], pad O ----------------
__global__ void packw_off(const float* __restrict__ src, fp16* __restrict__ h) {
    int o = blockIdx.x;
    int r = blockIdx.y * 256 + threadIdx.x;     // r = k*256 + c
    int c = r & 255, k = r >> 8;
    float v = (o < OFFC) ? src[((size_t)o * 256 + c) * 25 + k] : 0.0f;
    h[(size_t)o * R5 + r] = __float2half_rn(v);
}

// ---------------- weight pack (fused): [w_def | w_temp] k-major over RF ----------------
__global__ void packw_f(const float* __restrict__ wdef, const float* __restrict__ wtmp,
                        fp16* __restrict__ h) {
    int o = blockIdx.x;
    int r = blockIdx.y * 256 + threadIdx.x;
    float v;
    if (r < R5) {
        int c = r & 255, k = r >> 8;
        v = wdef[((size_t)o * 256 + c) * 25 + k];
    } else {
        int m = r - R5;
        int c = m & 255, q = m >> 8;
        v = wtmp[((size_t)o * 256 + c) * 27 + q];
    }
    h[(size_t)o * RF + r] = __float2half_rn(v);
}

// ---------------- bilinear sampler on xT -> Bs[t][p][k*256+c] ----------------
// block 256 = 32 p-lanes x 8 c-octets; grid (TT, 72, 4 deform-groups)
__global__ void __launch_bounds__(256) sample_k(const fp16* __restrict__ xT,
                                                const float* __restrict__ off,
                                                fp16* __restrict__ Bs) {
    int t = blockIdx.x, p0 = blockIdx.y * 32, dg = blockIdx.z;
    int oct = threadIdx.x & 7, pl = threadIdx.x >> 3;
    int p = p0 + pl, py = p / WWD, px = p % WWD;
    const fp16* xb = xT + (size_t)t * PP * 256 + dg * 64 + oct * 8;
    fp16* dstb = Bs + ((size_t)t * PP + p) * R5 + dg * 64 + oct * 8;
    #pragma unroll 1
    for (int k = 0; k < 25; k++) {
        const float* offy = off + ((size_t)t * OFFC + (dg * 25 + k) * 2) * PP;
        float sy = (float)(py + k / 5 - 2) + __ldg(offy + p);
        float sx = (float)(px + k % 5 - 2) + __ldg(offy + PP + p);
        float fy = floorf(sy), fx = floorf(sx);
        int y0 = (int)fy, x0 = (int)fx;
        float wy = sy - fy, wx = sx - fx;
        int y1 = y0 + 1, x1 = x0 + 1;
        float vy0 = (y0 >= 0 && y0 < HH) ? 1.0f : 0.0f;
        float vy1 = (y1 >= 0 && y1 < HH) ? 1.0f : 0.0f;
        float vx0 = (x0 >= 0 && x0 < WWD) ? 1.0f : 0.0f;
        float vx1 = (x1 >= 0 && x1 < WWD) ? 1.0f : 0.0f;
        int y0c = min(max(y0, 0), HH - 1), y1c = min(max(y1, 0), HH - 1);
        int x0c = min(max(x0, 0), WWD - 1), x1c = min(max(x1, 0), WWD - 1);
        float w00 = (1.0f - wy) * (1.0f - wx) * vy0 * vx0;
        float w01 = (1.0f - wy) * wx          * vy0 * vx1;
        float w10 = wy          * (1.0f - wx) * vy1 * vx0;
        float w11 = wy          * wx          * vy1 * vx1;
        const __half2* a = (const __half2*)(xb + (size_t)(y0c * WWD + x0c) * 256);
        const __half2* b = (const __half2*)(xb + (size_t)(y0c * WWD + x1c) * 256);
        const __half2* cq = (const __half2*)(xb + (size_t)(y1c * WWD + x0c) * 256);
        const __half2* d = (const __half2*)(xb + (size_t)(y1c * WWD + x1c) * 256);
        __half2 r[4];
        #pragma unroll
        for (int j = 0; j < 4; j++) {
            float2 fa = __half22float2(a[j]), fb = __half22float2(b[j]);
            float2 fc = __half22float2(cq[j]), fd = __half22float2(d[j]);
            float rx = w00 * fa.x + w01 * fb.x + w10 * fc.x + w11 * fd.x;
            float ry = w00 * fa.y + w01 * fb.y + w10 * fc.y + w11 * fd.y;
            r[j] = __floats2half2_rn(rx, ry);
        }
        *(uint4*)(dstb + k * 256) = *(uint4*)r;
    }
}

// ---------------- GEMM with implicit-im2col B producer ----------------
// MODE 0: offset conv — B fully implicit 1x5x5 from xT.
// MODE 1: fused     — chunks <100 explicit from Bs, >=100 implicit 3x3x3 from xT.
// Tile 128(o) x 128(p), K chunk 64 (128B rows), 3 stages, warp grid 4(m) x 2(n).
#define NSTAGE 3
#define STG    32768
#define GSMEM  (NSTAGE * STG)

template<int MODE>
__device__ __forceinline__ void loadB_chunk(
    uint32_t dstB, int ch, int t, const fp16* __restrict__ BsRow,
    const fp16* __restrict__ xT, int c8, int rb,
    const int* pj, const int* pyj, const int* pxj)
{
    if (MODE == 1 && ch < 100) {
        size_t rof = (size_t)ch * 64 + c8 * 8;
        #pragma unroll
        for (int j = 0; j < 4; j++) {
            int row = rb + 32 * j;
            cpa16(dstB + row * 128 + ((c8 ^ (row & 7)) << 4),
                  BsRow + (size_t)row * R5 + rof);
        }
    } else {
        int m = (MODE == 1) ? ch - 100 : ch;
        int kk = m >> 2, c0 = (m & 3) * 64;
        int dy, dx, tt;
        if (MODE == 0) { dy = kk / 5 - 2; dx = kk % 5 - 2; tt = t; }
        else { tt = t + kk / 9 - 1; int rq = kk % 9; dy = rq / 3 - 1; dx = rq % 3 - 1; }
        int tok = (tt >= 0 && tt < TT) ? 1 : 0;
        #pragma unroll
        for (int j = 0; j < 4; j++) {
            int row = rb + 32 * j;
            int y = pyj[j] + dy, x = pxj[j] + dx;
            int vld = (tok && y >= 0 && y < HH && x >= 0 && x < WWD) ? 16 : 0;
            size_t soff = vld ? ((size_t)(tt * PP + pj[j] + dy * WWD + dx) * 256
                                 + c0 + c8 * 8) : 0;
            cpa16z(dstB + row * 128 + ((c8 ^ (row & 7)) << 4), xT + soff, vld);
        }
    }
}

template<int MODE>
__global__ void __launch_bounds__(256, 1) gemm_mma(
    const fp16* __restrict__ Wh, const fp16* __restrict__ Bs,
    const fp16* __restrict__ xT,
    float* __restrict__ outp, int R, int Olim,
    long long o_stride, long long t_stride,
    const float* __restrict__ bias)
{
    extern __shared__ char smraw[];
    uint32_t sb = smem_u32(smraw);
    int tid = threadIdx.x, lane = tid & 31, wid = tid >> 5;
    int wm = wid & 3, wn = wid >> 2;
    int p0 = blockIdx.x * 128, t = blockIdx.y, o0 = blockIdx.z * 128;

    const fp16* gA = Wh + (size_t)o0 * R;
    const fp16* BsRow = Bs + ((size_t)t * PP + p0) * R5;

    int c8 = tid & 7;
    int rb = tid >> 3;
    int NC = R >> 6;

    int pj[4], pyj[4], pxj[4];
    #pragma unroll
    for (int j = 0; j < 4; j++) {
        pj[j] = p0 + rb + 32 * j;
        pyj[j] = pj[j] / WWD;
        pxj[j] = pj[j] % WWD;
    }

    int aRow = (lane & 7) + ((lane >> 3) & 1) * 8;
    int aKg  = (lane >> 4) & 1;
    int bRow = (lane & 7) + ((lane >> 4) & 1) * 8;
    int bKg  = (lane >> 3) & 1;

    float acc[2][8][4];
    #pragma unroll
    for (int i = 0; i < 2; i++)
        #pragma unroll
        for (int j = 0; j < 8; j++)
            #pragma unroll
            for (int q = 0; q < 4; q++) acc[i][j][q] = 0.0f;

    // prologue
    #pragma unroll
    for (int pc = 0; pc < 2; pc++) {
        uint32_t stb = sb + pc * STG;
        size_t rof = (size_t)(pc * 64) + c8 * 8;
        #pragma unroll
        for (int j = 0; j < 4; j++) {
            int row = rb + 32 * j;
            cpa16(stb + row * 128 + ((c8 ^ (row & 7)) << 4), gA + (size_t)row * R + rof);
        }
        loadB_chunk<MODE>(stb + 16384, pc, t, BsRow, xT, c8, rb, pj, pyj, pxj);
        asm volatile("cp.async.commit_group;" ::: "memory");
    }

    for (int ch = 0; ch < NC; ch++) {
        asm volatile("cp.async.wait_group 1;" ::: "memory");
        __syncthreads();
        uint32_t stb = sb + (ch % NSTAGE) * STG;

        #pragma unroll
        for (int kk = 0; kk < 4; kk++) {
            uint32_t ah[2][4], bh[8][2];
            #pragma unroll
            for (int mt = 0; mt < 2; mt++) {
                int row = wm * 32 + mt * 16 + aRow;
                ldsm4(ah[mt], stb + row * 128 + (((kk * 2 + aKg) ^ (row & 7)) << 4));
            }
            #pragma unroll
            for (int ng = 0; ng < 4; ng++) {
                int row = wn * 64 + ng * 16 + bRow;
                uint32_t r4[4];
                ldsm4(r4, stb + 16384 + row * 128 + (((kk * 2 + bKg) ^ (row & 7)) << 4));
                bh[ng * 2][0] = r4[0]; bh[ng * 2][1] = r4[1];
                bh[ng * 2 + 1][0] = r4[2]; bh[ng * 2 + 1][1] = r4[3];
            }
            #pragma unroll
            for (int mt = 0; mt < 2; mt++)
                #pragma unroll
                for (int nt = 0; nt < 8; nt++)
                    mma16816(acc[mt][nt], ah[mt], bh[nt]);
        }

        int nx = ch + 2;
        if (nx < NC) {
            uint32_t stb2 = sb + (nx % NSTAGE) * STG;
            size_t rof = (size_t)nx * 64 + c8 * 8;
            #pragma unroll
            for (int j = 0; j < 4; j++) {
                int row = rb + 32 * j;
                cpa16(stb2 + row * 128 + ((c8 ^ (row & 7)) << 4), gA + (size_t)row * R + rof);
            }
            loadB_chunk<MODE>(stb2 + 16384, nx, t, BsRow, xT, c8, rb, pj, pyj, pxj);
        }
        asm volatile("cp.async.commit_group;" ::: "memory");
    }

    // epilogue
    int er = lane >> 2, ec = (lane & 3) * 2;
    #pragma unroll
    for (int mt = 0; mt < 2; mt++) {
        int obase = o0 + wm * 32 + mt * 16 + er;
        #pragma unroll
        for (int h = 0; h < 2; h++) {
            int o = obase + h * 8;
            if (o < Olim) {
                float bv = (bias != nullptr) ? bias[o] : 0.0f;
                size_t rb2 = (size_t)o * o_stride + (size_t)t * t_stride + p0 + wn * 64 + ec;
                #pragma unroll
                for (int nt = 0; nt < 8; nt++) {
                    float2* dp = (float2*)(outp + rb2 + nt * 8);
                    float2 wv;
                    wv.x = acc[mt][nt][h * 2 + 0] + bv;
                    wv.y = acc[mt][nt][h * 2 + 1] + bv;
                    *dp = wv;
                }
            }
        }
    }
}

// ---------------- launch ----------------
extern "C" void kernel_launch(void* const* d_in, const int* in_sizes, int n_in,
                              void* d_out, int out_size) {
    (void)in_sizes; (void)n_in; (void)out_size;
    const float* x      = (const float*)d_in[0];
    const float* w_off  = (const float*)d_in[1];
    const float* w_def  = (const float*)d_in[2];
    const float* w_temp = (const float*)d_in[3];
    const float* b_temp = (const float*)d_in[4];
    float* out = (float*)d_out;

    fp16 *xTp, *Bsp, *wofh, *wfh;
    float* offp;
    cudaGetSymbolAddress((void**)&xTp,  g_xT);
    cudaGetSymbolAddress((void**)&Bsp,  g_Bs);
    cudaGetSymbolAddress((void**)&wofh, g_Woff_h);
    cudaGetSymbolAddress((void**)&wfh,  g_Wf_h);
    cudaGetSymbolAddress((void**)&offp, g_off);

    cudaFuncSetAttribute(gemm_mma<0>, cudaFuncAttributeMaxDynamicSharedMemorySize, GSMEM);
    cudaFuncSetAttribute(gemm_mma<1>, cudaFuncAttributeMaxDynamicSharedMemorySize, GSMEM);

    // fork: weight packs on side stream
    cudaEventRecord(g_fork, 0);
    cudaStreamWaitEvent(g_side, g_fork, 0);
    packw_off<<<dim3(256, 25), 256, 0, g_side>>>(w_off, wofh);
    cudaEventRecord(g_e1, g_side);
    packw_f<<<dim3(256, 52), 256, 0, g_side>>>(w_def, w_temp, wfh);
    cudaEventRecord(g_e2, g_side);

    // main: transpose -> offset GEMM (implicit B) -> sampler -> fused GEMM
    transpose_x<<<dim3(TT, 72, 8), 256>>>(x, xTp);
    cudaStreamWaitEvent(0, g_e1, 0);
    gemm_mma<0><<<dim3(18, TT, 2), 256, GSMEM>>>(
        wofh, xTp /*unused explicit*/, xTp, offp, R5, OFFC,
        PP, (long long)OFFC * PP, nullptr);

    sample_k<<<dim3(TT, 72, 4), 256>>>(xTp, offp, Bsp);

    cudaStreamWaitEvent(0, g_e2, 0);
    gemm_mma<1><<<dim3(18, TT, 2), 256, GSMEM>>>(
        wfh, Bsp, xTp, out, RF, 256, (long long)TT * PP, PP, b_temp);
}

// round 11
// speedup vs baseline: 7.4971x; 1.0146x over previous
#include <cuda_runtime.h>
#include <cuda_fp16.h>
#include <cstdint>

#define TT   4
#define HH   48
#define WWD  48
#define PP   2304          // 48*48
#define R5   6400          // 256*25
#define R3   6912          // 256*27
#define RF   13312         // R5 + R3 fused K
#define OFFC 200           // 4*2*25

typedef __half fp16;

// ---------------- scratch (static device globals; no allocation) ----------------
__device__ fp16 g_xT[(size_t)TT * PP * 256];  // [t][p][c] fp16 transpose of x (L2-resident)
__device__ fp16 g_Bs[(size_t)TT * PP * R5];   // [t][p][k*256+c] sampled B (k-major)
__device__ fp16 g_Woff_h[256 * R5];           // [o][k*256+c]
__device__ fp16 g_Wf_h[256 * RF];             // [o][r] k-major both halves
__device__ float g_off[TT * OFFC * PP];       // [t][och][p]

// ---------------- side stream: LAZY init on first kernel_launch (never in static ctor —
// pre-main CUDA calls latch error 802 "system not yet initialized" on GB300) ----------------
static cudaStream_t g_side = nullptr;
static cudaEvent_t g_fork, g_e1, g_e2;

// ---------------- helpers ----------------
__device__ __forceinline__ uint32_t smem_u32(const void* p) {
    uint32_t a;
    asm("{ .reg .u64 t; cvta.to.shared.u64 t, %1; cvt.u32.u64 %0, t; }" : "=r"(a) : "l"(p));
    return a;
}
__device__ __forceinline__ void cpa16(uint32_t dst, const void* src) {
    asm volatile("cp.async.cg.shared.global [%0], [%1], 16;" :: "r"(dst), "l"(src) : "memory");
}
__device__ __forceinline__ void cpa16z(uint32_t dst, const void* src, int vld16) {
    asm volatile("cp.async.cg.shared.global [%0], [%1], 16, %2;"
                 :: "r"(dst), "l"(src), "r"(vld16) : "memory");
}
__device__ __forceinline__ void ldsm4(uint32_t* r, uint32_t a) {
    asm volatile("ldmatrix.sync.aligned.m8n8.x4.shared.b16 {%0,%1,%2,%3}, [%4];"
                 : "=r"(r[0]), "=r"(r[1]), "=r"(r[2]), "=r"(r[3]) : "r"(a));
}
__device__ __forceinline__ void mma16816(float* c, const uint32_t* a, const uint32_t* b) {
    asm volatile("mma.sync.aligned.m16n8k16.row.col.f32.f16.f16.f32 "
                 "{%0,%1,%2,%3}, {%4,%5,%6,%7}, {%8,%9}, {%0,%1,%2,%3};"
                 : "+f"(c[0]), "+f"(c[1]), "+f"(c[2]), "+f"(c[3])
                 : "r"(a[0]), "r"(a[1]), "r"(a[2]), "r"(a[3]), "r"(b[0]), "r"(b[1]));
}

// ---------------- x transpose: x[c][t][p] fp32 -> xT[t][p][c] fp16 ----------------
__global__ void __launch_bounds__(256) transpose_x(const float* __restrict__ x,
                                                   fp16* __restrict__ xT) {
    __shared__ float tl[32][33];
    int t = blockIdx.x, p0 = blockIdx.y * 32, c0 = blockIdx.z * 32;
    int tx = threadIdx.x & 31, ty = threadIdx.x >> 5;
    #pragma unroll
    for (int i = ty; i < 32; i += 8)
        tl[i][tx] = x[((size_t)(c0 + i) * TT + t) * PP + p0 + tx];
    __syncthreads();
    #pragma unroll
    for (int i = ty; i < 32; i += 8)
        xT[((size_t)t * PP + p0 + i) * 256 + c0 + tx] = __float2half_rn(tl[tx][i]);
}

// ---------------- weight pack (offset): w_off[o][c][k] -> [o][k*256+c], pad O ----------------
__global__ void packw_off(const float* __restrict__ src, fp16* __restrict__ h) {
    int o = blockIdx.x;
    int r = blockIdx.y * 256 + threadIdx.x;     // r = k*256 + c
    int c = r & 255, k = r >> 8;
    float v = (o < OFFC) ? src[((size_t)o * 256 + c) * 25 + k] : 0.0f;
    h[(size_t)o * R5 + r] = __float2half_rn(v);
}

// ---------------- weight pack (fused): [w_def | w_temp] k-major over RF ----------------
__global__ void packw_f(const float* __restrict__ wdef, const float* __restrict__ wtmp,
                        fp16* __restrict__ h) {
    int o = blockIdx.x;
    int r = blockIdx.y * 256 + threadIdx.x;
    float v;
    if (r < R5) {
        int c = r & 255, k = r >> 8;
        v = wdef[((size_t)o * 256 + c) * 25 + k];
    } else {
        int m = r - R5;
        int c = m & 255, q = m >> 8;
        v = wtmp[((size_t)o * 256 + c) * 27 + q];
    }
    h[(size_t)o * RF + r] = __float2half_rn(v);
}

// ---------------- bilinear sampler on xT -> Bs[t][p][k*256+c] ----------------
__global__ void __launch_bounds__(256) sample_k(const fp16* __restrict__ xT,
                                                const float* __restrict__ off,
                                                fp16* __restrict__ Bs) {
    int t = blockIdx.x, p0 = blockIdx.y * 32, dg = blockIdx.z;
    int oct = threadIdx.x & 7, pl = threadIdx.x >> 3;
    int p = p0 + pl, py = p / WWD, px = p % WWD;
    const fp16* xb = xT + (size_t)t * PP * 256 + dg * 64 + oct * 8;
    fp16* dstb = Bs + ((size_t)t * PP + p) * R5 + dg * 64 + oct * 8;
    #pragma unroll 1
    for (int k = 0; k < 25; k++) {
        const float* offy = off + ((size_t)t * OFFC + (dg * 25 + k) * 2) * PP;
        float sy = (float)(py + k / 5 - 2) + __ldg(offy + p);
        float sx = (float)(px + k % 5 - 2) + __ldg(offy + PP + p);
        float fy = floorf(sy), fx = floorf(sx);
        int y0 = (int)fy, x0 = (int)fx;
        float wy = sy - fy, wx = sx - fx;
        int y1 = y0 + 1, x1 = x0 + 1;
        float vy0 = (y0 >= 0 && y0 < HH) ? 1.0f : 0.0f;
        float vy1 = (y1 >= 0 && y1 < HH) ? 1.0f : 0.0f;
        float vx0 = (x0 >= 0 && x0 < WWD) ? 1.0f : 0.0f;
        float vx1 = (x1 >= 0 && x1 < WWD) ? 1.0f : 0.0f;
        int y0c = min(max(y0, 0), HH - 1), y1c = min(max(y1, 0), HH - 1);
        int x0c = min(max(x0, 0), WWD - 1), x1c = min(max(x1, 0), WWD - 1);
        float w00 = (1.0f - wy) * (1.0f - wx) * vy0 * vx0;
        float w01 = (1.0f - wy) * wx          * vy0 * vx1;
        float w10 = wy          * (1.0f - wx) * vy1 * vx0;
        float w11 = wy          * wx          * vy1 * vx1;
        const __half2* a = (const __half2*)(xb + (size_t)(y0c * WWD + x0c) * 256);
        const __half2* b = (const __half2*)(xb + (size_t)(y0c * WWD + x1c) * 256);
        const __half2* cq = (const __half2*)(xb + (size_t)(y1c * WWD + x0c) * 256);
        const __half2* d = (const __half2*)(xb + (size_t)(y1c * WWD + x1c) * 256);
        __half2 r[4];
        #pragma unroll
        for (int j = 0; j < 4; j++) {
            float2 fa = __half22float2(a[j]), fb = __half22float2(b[j]);
            float2 fc = __half22float2(cq[j]), fd = __half22float2(d[j]);
            float rx = w00 * fa.x + w01 * fb.x + w10 * fc.x + w11 * fd.x;
            float ry = w00 * fa.y + w01 * fb.y + w10 * fc.y + w11 * fd.y;
            r[j] = __floats2half2_rn(rx, ry);
        }
        *(uint4*)(dstb + k * 256) = *(uint4*)r;
    }
}

// ---------------- GEMM with implicit-im2col B producer ----------------
// Tile 128(o) x 64(p), K chunk 64, 4 stages (24KB each = 96KB), 2 CTAs/SM.
// Warp grid 4(m) x 2(n): warp tile 32x32.
// MODE 0: offset conv — B fully implicit 1x5x5 from xT.
// MODE 1: fused — chunks <100 explicit from Bs, >=100 implicit 3x3x3 from xT.
#define NSTAGE 4
#define STG    24576
#define GSMEM  (NSTAGE * STG)

template<int MODE>
__device__ __forceinline__ void loadB_chunk(
    uint32_t dstB, int ch, int t, const fp16* __restrict__ BsRow,
    const fp16* __restrict__ xT, int c8, int rb,
    const int* pj, const int* pyj, const int* pxj)
{
    if (MODE == 1 && ch < 100) {
        size_t rof = (size_t)ch * 64 + c8 * 8;
        #pragma unroll
        for (int j = 0; j < 2; j++) {
            int row = rb + 32 * j;
            cpa16(dstB + row * 128 + ((c8 ^ (row & 7)) << 4),
                  BsRow + (size_t)row * R5 + rof);
        }
    } else {
        int m = (MODE == 1) ? ch - 100 : ch;
        int kk = m >> 2, c0 = (m & 3) * 64;
        int dy, dx, tt;
        if (MODE == 0) { dy = kk / 5 - 2; dx = kk % 5 - 2; tt = t; }
        else { tt = t + kk / 9 - 1; int rq = kk % 9; dy = rq / 3 - 1; dx = rq % 3 - 1; }
        int tok = (tt >= 0 && tt < TT) ? 1 : 0;
        #pragma unroll
        for (int j = 0; j < 2; j++) {
            int row = rb + 32 * j;
            int y = pyj[j] + dy, x = pxj[j] + dx;
            int vld = (tok && y >= 0 && y < HH && x >= 0 && x < WWD) ? 16 : 0;
            size_t soff = vld ? ((size_t)(tt * PP + pj[j] + dy * WWD + dx) * 256
                                 + c0 + c8 * 8) : 0;
            cpa16z(dstB + row * 128 + ((c8 ^ (row & 7)) << 4), xT + soff, vld);
        }
    }
}

template<int MODE>
__global__ void __launch_bounds__(256, 2) gemm_mma(
    const fp16* __restrict__ Wh, const fp16* __restrict__ Bs,
    const fp16* __restrict__ xT,
    float* __restrict__ outp, int R, int Olim,
    long long o_stride, long long t_stride,
    const float* __restrict__ bias)
{
    extern __shared__ char smraw[];
    uint32_t sb = smem_u32(smraw);
    int tid = threadIdx.x, lane = tid & 31, wid = tid >> 5;
    int wm = wid & 3, wn = wid >> 2;               // 4 x 2 -> warp tile 32(m) x 32(n)
    int p0 = blockIdx.x * 64, t = blockIdx.y, o0 = blockIdx.z * 128;

    const fp16* gA = Wh + (size_t)o0 * R;
    const fp16* BsRow = Bs + ((size_t)t * PP + p0) * R5;

    int c8 = tid & 7;
    int rb = tid >> 3;             // 0..31
    int NC = R >> 6;

    int pj[2], pyj[2], pxj[2];
    #pragma unroll
    for (int j = 0; j < 2; j++) {
        pj[j] = p0 + rb + 32 * j;
        pyj[j] = pj[j] / WWD;
        pxj[j] = pj[j] % WWD;
    }

    int aRow = (lane & 7) + ((lane >> 3) & 1) * 8;
    int aKg  = (lane >> 4) & 1;
    int bRow = (lane & 7) + ((lane >> 4) & 1) * 8;
    int bKg  = (lane >> 3) & 1;

    float acc[2][4][4];
    #pragma unroll
    for (int i = 0; i < 2; i++)
        #pragma unroll
        for (int j = 0; j < 4; j++)
            #pragma unroll
            for (int q = 0; q < 4; q++) acc[i][j][q] = 0.0f;

    // prologue: chunks 0..2
    #pragma unroll
    for (int pc = 0; pc < NSTAGE - 1; pc++) {
        uint32_t stb = sb + pc * STG;
        size_t rof = (size_t)(pc * 64) + c8 * 8;
        #pragma unroll
        for (int j = 0; j < 4; j++) {
            int row = rb + 32 * j;
            cpa16(stb + row * 128 + ((c8 ^ (row & 7)) << 4), gA + (size_t)row * R + rof);
        }
        loadB_chunk<MODE>(stb + 16384, pc, t, BsRow, xT, c8, rb, pj, pyj, pxj);
        asm volatile("cp.async.commit_group;" ::: "memory");
    }

    for (int ch = 0; ch < NC; ch++) {
        asm volatile("cp.async.wait_group 2;" ::: "memory");
        __syncthreads();
        uint32_t stb = sb + (ch % NSTAGE) * STG;

        #pragma unroll
        for (int kk = 0; kk < 4; kk++) {
            uint32_t ah[2][4], bh[4][2];
            #pragma unroll
            for (int mt = 0; mt < 2; mt++) {
                int row = wm * 32 + mt * 16 + aRow;
                ldsm4(ah[mt], stb + row * 128 + (((kk * 2 + aKg) ^ (row & 7)) << 4));
            }
            #pragma unroll
            for (int ng = 0; ng < 2; ng++) {
                int row = wn * 32 + ng * 16 + bRow;
                uint32_t r4[4];
                ldsm4(r4, stb + 16384 + row * 128 + (((kk * 2 + bKg) ^ (row & 7)) << 4));
                bh[ng * 2][0] = r4[0]; bh[ng * 2][1] = r4[1];
                bh[ng * 2 + 1][0] = r4[2]; bh[ng * 2 + 1][1] = r4[3];
            }
            #pragma unroll
            for (int mt = 0; mt < 2; mt++)
                #pragma unroll
                for (int nt = 0; nt < 4; nt++)
                    mma16816(acc[mt][nt], ah[mt], bh[nt]);
        }

        int nx = ch + NSTAGE - 1;
        if (nx < NC) {
            uint32_t stb2 = sb + (nx % NSTAGE) * STG;
            size_t rof = (size_t)nx * 64 + c8 * 8;
            #pragma unroll
            for (int j = 0; j < 4; j++) {
                int row = rb + 32 * j;
                cpa16(stb2 + row * 128 + ((c8 ^ (row & 7)) << 4), gA + (size_t)row * R + rof);
            }
            loadB_chunk<MODE>(stb2 + 16384, nx, t, BsRow, xT, c8, rb, pj, pyj, pxj);
        }
        asm volatile("cp.async.commit_group;" ::: "memory");
    }

    // epilogue
    int er = lane >> 2, ec = (lane & 3) * 2;
    #pragma unroll
    for (int mt = 0; mt < 2; mt++) {
        int obase = o0 + wm * 32 + mt * 16 + er;
        #pragma unroll
        for (int h = 0; h < 2; h++) {
            int o = obase + h * 8;
            if (o < Olim) {
                float bv = (bias != nullptr) ? bias[o] : 0.0f;
                size_t rb2 = (size_t)o * o_stride + (size_t)t * t_stride + p0 + wn * 32 + ec;
                #pragma unroll
                for (int nt = 0; nt < 4; nt++) {
                    float2* dp = (float2*)(outp + rb2 + nt * 8);
                    float2 wv;
                    wv.x = acc[mt][nt][h * 2 + 0] + bv;
                    wv.y = acc[mt][nt][h * 2 + 1] + bv;
                    *dp = wv;
                }
            }
        }
    }
}

// ---------------- launch ----------------
extern "C" void kernel_launch(void* const* d_in, const int* in_sizes, int n_in,
                              void* d_out, int out_size) {
    (void)in_sizes; (void)n_in; (void)out_size;
    const float* x      = (const float*)d_in[0];
    const float* w_off  = (const float*)d_in[1];
    const float* w_def  = (const float*)d_in[2];
    const float* w_temp = (const float*)d_in[3];
    const float* b_temp = (const float*)d_in[4];
    float* out = (float*)d_out;

    // Lazy one-time init: first call is the (uncaptured) correctness run, so
    // stream/event creation never happens during graph capture and never pre-main.
    if (g_side == nullptr) {
        cudaStreamCreateWithFlags(&g_side, cudaStreamNonBlocking);
        cudaEventCreateWithFlags(&g_fork, cudaEventDisableTiming);
        cudaEventCreateWithFlags(&g_e1, cudaEventDisableTiming);
        cudaEventCreateWithFlags(&g_e2, cudaEventDisableTiming);
        cudaFuncSetAttribute(gemm_mma<0>, cudaFuncAttributeMaxDynamicSharedMemorySize, GSMEM);
        cudaFuncSetAttribute(gemm_mma<1>, cudaFuncAttributeMaxDynamicSharedMemorySize, GSMEM);
    }

    fp16 *xTp, *Bsp, *wofh, *wfh;
    float* offp;
    cudaGetSymbolAddress((void**)&xTp,  g_xT);
    cudaGetSymbolAddress((void**)&Bsp,  g_Bs);
    cudaGetSymbolAddress((void**)&wofh, g_Woff_h);
    cudaGetSymbolAddress((void**)&wfh,  g_Wf_h);
    cudaGetSymbolAddress((void**)&offp, g_off);

    // fork: weight packs on side stream
    cudaEventRecord(g_fork, 0);
    cudaStreamWaitEvent(g_side, g_fork, 0);
    packw_off<<<dim3(256, 25), 256, 0, g_side>>>(w_off, wofh);
    cudaEventRecord(g_e1, g_side);
    packw_f<<<dim3(256, 52), 256, 0, g_side>>>(w_def, w_temp, wfh);
    cudaEventRecord(g_e2, g_side);

    // main: transpose -> offset GEMM (implicit B) -> sampler -> fused GEMM
    transpose_x<<<dim3(TT, 72, 8), 256>>>(x, xTp);
    cudaStreamWaitEvent(0, g_e1, 0);
    gemm_mma<0><<<dim3(36, TT, 2), 256, GSMEM>>>(
        wofh, xTp /*unused explicit*/, xTp, offp, R5, OFFC,
        PP, (long long)OFFC * PP, nullptr);

    sample_k<<<dim3(TT, 72, 4), 256>>>(xTp, offp, Bsp);

    cudaStreamWaitEvent(0, g_e2, 0);
    gemm_mma<1><<<dim3(36, TT, 2), 256, GSMEM>>>(
        wfh, Bsp, xTp, out, RF, 256, (long long)TT * PP, PP, b_temp);
}

// round 12
// speedup vs baseline: 7.8732x; 1.0502x over previous
#include <cuda_runtime.h>
#include <cuda_fp16.h>
#include <cstdint>

#define TT   4
#define HH   48
#define WWD  48
#define PP   2304          // 48*48
#define R5   6400          // 256*25
#define R3   6912          // 256*27
#define RF   13312         // R5 + R3 fused K
#define OFFC 200           // 4*2*25

typedef __half fp16;

// ---------------- scratch (static device globals; no allocation) ----------------
__device__ fp16 g_xT[(size_t)TT * PP * 256];  // [t][p][c] fp16 transpose of x (L2-resident)
__device__ fp16 g_Bs[(size_t)TT * PP * R5];   // [t][p][k*256+c] sampled B (k-major)
__device__ fp16 g_Woff_h[256 * R5];           // [o][k*256+c]
__device__ fp16 g_Wf_h[256 * RF];             // [o][r] k-major both halves
__device__ float g_off[TT * OFFC * PP];       // [t][och][p]

// ---------------- side stream: LAZY init on first kernel_launch (never in static ctor —
// pre-main CUDA calls latch error 802 "system not yet initialized" on GB300) ----------------
static cudaStream_t g_side = nullptr;
static cudaEvent_t g_fork, g_e1, g_e2;

// ---------------- helpers ----------------
__device__ __forceinline__ uint32_t smem_u32(const void* p) {
    uint32_t a;
    asm("{ .reg .u64 t; cvta.to.shared.u64 t, %1; cvt.u32.u64 %0, t; }" : "=r"(a) : "l"(p));
    return a;
}
__device__ __forceinline__ void cpa16(uint32_t dst, const void* src) {
    asm volatile("cp.async.cg.shared.global [%0], [%1], 16;" :: "r"(dst), "l"(src) : "memory");
}
__device__ __forceinline__ void cpa16z(uint32_t dst, const void* src, int vld16) {
    asm volatile("cp.async.cg.shared.global [%0], [%1], 16, %2;"
                 :: "r"(dst), "l"(src), "r"(vld16) : "memory");
}
__device__ __forceinline__ void ldsm4(uint32_t* r, uint32_t a) {
    asm volatile("ldmatrix.sync.aligned.m8n8.x4.shared.b16 {%0,%1,%2,%3}, [%4];"
                 : "=r"(r[0]), "=r"(r[1]), "=r"(r[2]), "=r"(r[3]) : "r"(a));
}
__device__ __forceinline__ void mma16816(float* c, const uint32_t* a, const uint32_t* b) {
    asm volatile("mma.sync.aligned.m16n8k16.row.col.f32.f16.f16.f32 "
                 "{%0,%1,%2,%3}, {%4,%5,%6,%7}, {%8,%9}, {%0,%1,%2,%3};"
                 : "+f"(c[0]), "+f"(c[1]), "+f"(c[2]), "+f"(c[3])
                 : "r"(a[0]), "r"(a[1]), "r"(a[2]), "r"(a[3]), "r"(b[0]), "r"(b[1]));
}

// ---------------- x transpose: x[c][t][p] fp32 -> xT[t][p][c] fp16 ----------------
__global__ void __launch_bounds__(256) transpose_x(const float* __restrict__ x,
                                                   fp16* __restrict__ xT) {
    __shared__ float tl[32][33];
    int t = blockIdx.x, p0 = blockIdx.y * 32, c0 = blockIdx.z * 32;
    int tx = threadIdx.x & 31, ty = threadIdx.x >> 5;
    #pragma unroll
    for (int i = ty; i < 32; i += 8)
        tl[i][tx] = x[((size_t)(c0 + i) * TT + t) * PP + p0 + tx];
    __syncthreads();
    #pragma unroll
    for (int i = ty; i < 32; i += 8)
        xT[((size_t)t * PP + p0 + i) * 256 + c0 + tx] = __float2half_rn(tl[tx][i]);
}

// ---------------- weight pack (offset): w_off[o][c][k] -> [o][k*256+c], pad O ----------------
__global__ void packw_off(const float* __restrict__ src, fp16* __restrict__ h) {
    int o = blockIdx.x;
    int r = blockIdx.y * 256 + threadIdx.x;     // r = k*256 + c
    int c = r & 255, k = r >> 8;
    float v = (o < OFFC) ? src[((size_t)o * 256 + c) * 25 + k] : 0.0f;
    h[(size_t)o * R5 + r] = __float2half_rn(v);
}

// ---------------- weight pack (fused): [w_def | w_temp] k-major over RF ----------------
__global__ void packw_f(const float* __restrict__ wdef, const float* __restrict__ wtmp,
                        fp16* __restrict__ h) {
    int o = blockIdx.x;
    int r = blockIdx.y * 256 + threadIdx.x;
    float v;
    if (r < R5) {
        int c = r & 255, k = r >> 8;
        v = wdef[((size_t)o * 256 + c) * 25 + k];
    } else {
        int m = r - R5;
        int c = m & 255, q = m >> 8;
        v = wtmp[((size_t)o * 256 + c) * 27 + q];
    }
    h[(size_t)o * RF + r] = __float2half_rn(v);
}

// ---------------- bilinear sampler on xT -> Bs[t][p][k*256+c] ----------------
__global__ void __launch_bounds__(256) sample_k(const fp16* __restrict__ xT,
                                                const float* __restrict__ off,
                                                fp16* __restrict__ Bs) {
    int t = blockIdx.x, p0 = blockIdx.y * 32, dg = blockIdx.z;
    int oct = threadIdx.x & 7, pl = threadIdx.x >> 3;
    int p = p0 + pl, py = p / WWD, px = p % WWD;
    const fp16* xb = xT + (size_t)t * PP * 256 + dg * 64 + oct * 8;
    fp16* dstb = Bs + ((size_t)t * PP + p) * R5 + dg * 64 + oct * 8;
    #pragma unroll 1
    for (int k = 0; k < 25; k++) {
        const float* offy = off + ((size_t)t * OFFC + (dg * 25 + k) * 2) * PP;
        float sy = (float)(py + k / 5 - 2) + __ldg(offy + p);
        float sx = (float)(px + k % 5 - 2) + __ldg(offy + PP + p);
        float fy = floorf(sy), fx = floorf(sx);
        int y0 = (int)fy, x0 = (int)fx;
        float wy = sy - fy, wx = sx - fx;
        int y1 = y0 + 1, x1 = x0 + 1;
        float vy0 = (y0 >= 0 && y0 < HH) ? 1.0f : 0.0f;
        float vy1 = (y1 >= 0 && y1 < HH) ? 1.0f : 0.0f;
        float vx0 = (x0 >= 0 && x0 < WWD) ? 1.0f : 0.0f;
        float vx1 = (x1 >= 0 && x1 < WWD) ? 1.0f : 0.0f;
        int y0c = min(max(y0, 0), HH - 1), y1c = min(max(y1, 0), HH - 1);
        int x0c = min(max(x0, 0), WWD - 1), x1c = min(max(x1, 0), WWD - 1);
        float w00 = (1.0f - wy) * (1.0f - wx) * vy0 * vx0;
        float w01 = (1.0f - wy) * wx          * vy0 * vx1;
        float w10 = wy          * (1.0f - wx) * vy1 * vx0;
        float w11 = wy          * wx          * vy1 * vx1;
        const __half2* a = (const __half2*)(xb + (size_t)(y0c * WWD + x0c) * 256);
        const __half2* b = (const __half2*)(xb + (size_t)(y0c * WWD + x1c) * 256);
        const __half2* cq = (const __half2*)(xb + (size_t)(y1c * WWD + x0c) * 256);
        const __half2* d = (const __half2*)(xb + (size_t)(y1c * WWD + x1c) * 256);
        __half2 r[4];
        #pragma unroll
        for (int j = 0; j < 4; j++) {
            float2 fa = __half22float2(a[j]), fb = __half22float2(b[j]);
            float2 fc = __half22float2(cq[j]), fd = __half22float2(d[j]);
            float rx = w00 * fa.x + w01 * fb.x + w10 * fc.x + w11 * fd.x;
            float ry = w00 * fa.y + w01 * fb.y + w10 * fc.y + w11 * fd.y;
            r[j] = __floats2half2_rn(rx, ry);
        }
        *(uint4*)(dstb + k * 256) = *(uint4*)r;
    }
}

// ---------------- GEMM: tile 128(o) x 128(p), 4 warps, warp tile 64x64 ----------------
// K chunk 64, 4 stages (32KB each = 128KB), grid ~1 CTA/SM.
// MMA:LDSM ratio 4.0 (32 HMMA per 8 LDSM per kk) — halves L1 wavefront load.
// MODE 0: offset conv — B fully implicit 1x5x5 from xT.
// MODE 1: fused — chunks <100 explicit from Bs, >=100 implicit 3x3x3 from xT.
#define NSTAGE 4
#define STG    32768
#define GSMEM  (NSTAGE * STG)

template<int MODE>
__device__ __forceinline__ void loadB_chunk(
    uint32_t dstB, int ch, int t, const fp16* __restrict__ BsRow,
    const fp16* __restrict__ xT, int c8, int rb,
    const int* pj, const int* pyj, const int* pxj)
{
    if (MODE == 1 && ch < 100) {
        size_t rof = (size_t)ch * 64 + c8 * 8;
        #pragma unroll
        for (int j = 0; j < 8; j++) {
            int row = rb + 16 * j;
            cpa16(dstB + row * 128 + ((c8 ^ (row & 7)) << 4),
                  BsRow + (size_t)row * R5 + rof);
        }
    } else {
        int m = (MODE == 1) ? ch - 100 : ch;
        int kk = m >> 2, c0 = (m & 3) * 64;
        int dy, dx, tt;
        if (MODE == 0) { dy = kk / 5 - 2; dx = kk % 5 - 2; tt = t; }
        else { tt = t + kk / 9 - 1; int rq = kk % 9; dy = rq / 3 - 1; dx = rq % 3 - 1; }
        int tok = (tt >= 0 && tt < TT) ? 1 : 0;
        #pragma unroll
        for (int j = 0; j < 8; j++) {
            int row = rb + 16 * j;
            int y = pyj[j] + dy, x = pxj[j] + dx;
            int vld = (tok && y >= 0 && y < HH && x >= 0 && x < WWD) ? 16 : 0;
            size_t soff = vld ? ((size_t)(tt * PP + pj[j] + dy * WWD + dx) * 256
                                 + c0 + c8 * 8) : 0;
            cpa16z(dstB + row * 128 + ((c8 ^ (row & 7)) << 4), xT + soff, vld);
        }
    }
}

template<int MODE>
__global__ void __launch_bounds__(128, 1) gemm_mma(
    const fp16* __restrict__ Wh, const fp16* __restrict__ Bs,
    const fp16* __restrict__ xT,
    float* __restrict__ outp, int R, int Olim,
    long long o_stride, long long t_stride,
    const float* __restrict__ bias)
{
    extern __shared__ char smraw[];
    uint32_t sb = smem_u32(smraw);
    int tid = threadIdx.x, lane = tid & 31, wid = tid >> 5;
    int wm = wid & 1, wn = wid >> 1;               // 2 x 2 -> warp tile 64(m) x 64(n)
    int p0 = blockIdx.x * 128, t = blockIdx.y, o0 = blockIdx.z * 128;

    const fp16* gA = Wh + (size_t)o0 * R;
    const fp16* BsRow = Bs + ((size_t)t * PP + p0) * R5;

    int c8 = tid & 7;
    int rb = tid >> 3;             // 0..15
    int NC = R >> 6;

    int pj[8], pyj[8], pxj[8];
    #pragma unroll
    for (int j = 0; j < 8; j++) {
        pj[j] = p0 + rb + 16 * j;
        pyj[j] = pj[j] / WWD;
        pxj[j] = pj[j] % WWD;
    }

    int aRow = (lane & 7) + ((lane >> 3) & 1) * 8;
    int aKg  = (lane >> 4) & 1;
    int bRow = (lane & 7) + ((lane >> 4) & 1) * 8;
    int bKg  = (lane >> 3) & 1;

    float acc[4][8][4];
    #pragma unroll
    for (int i = 0; i < 4; i++)
        #pragma unroll
        for (int j = 0; j < 8; j++)
            #pragma unroll
            for (int q = 0; q < 4; q++) acc[i][j][q] = 0.0f;

    // prologue: chunks 0..2
    #pragma unroll
    for (int pc = 0; pc < NSTAGE - 1; pc++) {
        uint32_t stb = sb + pc * STG;
        size_t rof = (size_t)(pc * 64) + c8 * 8;
        #pragma unroll
        for (int j = 0; j < 8; j++) {
            int row = rb + 16 * j;
            cpa16(stb + row * 128 + ((c8 ^ (row & 7)) << 4), gA + (size_t)row * R + rof);
        }
        loadB_chunk<MODE>(stb + 16384, pc, t, BsRow, xT, c8, rb, pj, pyj, pxj);
        asm volatile("cp.async.commit_group;" ::: "memory");
    }

    for (int ch = 0; ch < NC; ch++) {
        asm volatile("cp.async.wait_group 2;" ::: "memory");
        __syncthreads();
        uint32_t stb = sb + (ch % NSTAGE) * STG;

        #pragma unroll
        for (int kk = 0; kk < 4; kk++) {
            uint32_t ah[4][4], bh[8][2];
            #pragma unroll
            for (int mt = 0; mt < 4; mt++) {
                int row = wm * 64 + mt * 16 + aRow;
                ldsm4(ah[mt], stb + row * 128 + (((kk * 2 + aKg) ^ (row & 7)) << 4));
            }
            #pragma unroll
            for (int ng = 0; ng < 4; ng++) {
                int row = wn * 64 + ng * 16 + bRow;
                uint32_t r4[4];
                ldsm4(r4, stb + 16384 + row * 128 + (((kk * 2 + bKg) ^ (row & 7)) << 4));
                bh[ng * 2][0] = r4[0]; bh[ng * 2][1] = r4[1];
                bh[ng * 2 + 1][0] = r4[2]; bh[ng * 2 + 1][1] = r4[3];
            }
            #pragma unroll
            for (int mt = 0; mt < 4; mt++)
                #pragma unroll
                for (int nt = 0; nt < 8; nt++)
                    mma16816(acc[mt][nt], ah[mt], bh[nt]);
        }

        int nx = ch + NSTAGE - 1;
        if (nx < NC) {
            uint32_t stb2 = sb + (nx % NSTAGE) * STG;
            size_t rof = (size_t)nx * 64 + c8 * 8;
            #pragma unroll
            for (int j = 0; j < 8; j++) {
                int row = rb + 16 * j;
                cpa16(stb2 + row * 128 + ((c8 ^ (row & 7)) << 4), gA + (size_t)row * R + rof);
            }
            loadB_chunk<MODE>(stb2 + 16384, nx, t, BsRow, xT, c8, rb, pj, pyj, pxj);
        }
        asm volatile("cp.async.commit_group;" ::: "memory");
    }

    // epilogue
    int er = lane >> 2, ec = (lane & 3) * 2;
    #pragma unroll
    for (int mt = 0; mt < 4; mt++) {
        int obase = o0 + wm * 64 + mt * 16 + er;
        #pragma unroll
        for (int h = 0; h < 2; h++) {
            int o = obase + h * 8;
            if (o < Olim) {
                float bv = (bias != nullptr) ? bias[o] : 0.0f;
                size_t rb2 = (size_t)o * o_stride + (size_t)t * t_stride + p0 + wn * 64 + ec;
                #pragma unroll
                for (int nt = 0; nt < 8; nt++) {
                    float2* dp = (float2*)(outp + rb2 + nt * 8);
                    float2 wv;
                    wv.x = acc[mt][nt][h * 2 + 0] + bv;
                    wv.y = acc[mt][nt][h * 2 + 1] + bv;
                    *dp = wv;
                }
            }
        }
    }
}

// ---------------- launch ----------------
extern "C" void kernel_launch(void* const* d_in, const int* in_sizes, int n_in,
                              void* d_out, int out_size) {
    (void)in_sizes; (void)n_in; (void)out_size;
    const float* x      = (const float*)d_in[0];
    const float* w_off  = (const float*)d_in[1];
    const float* w_def  = (const float*)d_in[2];
    const float* w_temp = (const float*)d_in[3];
    const float* b_temp = (const float*)d_in[4];
    float* out = (float*)d_out;

    // Lazy one-time init (first call is the uncaptured correctness run).
    if (g_side == nullptr) {
        cudaStreamCreateWithFlags(&g_side, cudaStreamNonBlocking);
        cudaEventCreateWithFlags(&g_fork, cudaEventDisableTiming);
        cudaEventCreateWithFlags(&g_e1, cudaEventDisableTiming);
        cudaEventCreateWithFlags(&g_e2, cudaEventDisableTiming);
        cudaFuncSetAttribute(gemm_mma<0>, cudaFuncAttributeMaxDynamicSharedMemorySize, GSMEM);
        cudaFuncSetAttribute(gemm_mma<1>, cudaFuncAttributeMaxDynamicSharedMemorySize, GSMEM);
    }

    fp16 *xTp, *Bsp, *wofh, *wfh;
    float* offp;
    cudaGetSymbolAddress((void**)&xTp,  g_xT);
    cudaGetSymbolAddress((void**)&Bsp,  g_Bs);
    cudaGetSymbolAddress((void**)&wofh, g_Woff_h);
    cudaGetSymbolAddress((void**)&wfh,  g_Wf_h);
    cudaGetSymbolAddress((void**)&offp, g_off);

    // fork: weight packs on side stream
    cudaEventRecord(g_fork, 0);
    cudaStreamWaitEvent(g_side, g_fork, 0);
    packw_off<<<dim3(256, 25), 256, 0, g_side>>>(w_off, wofh);
    cudaEventRecord(g_e1, g_side);
    packw_f<<<dim3(256, 52), 256, 0, g_side>>>(w_def, w_temp, wfh);
    cudaEventRecord(g_e2, g_side);

    // main: transpose -> offset GEMM (implicit B) -> sampler -> fused GEMM
    transpose_x<<<dim3(TT, 72, 8), 256>>>(x, xTp);
    cudaStreamWaitEvent(0, g_e1, 0);
    gemm_mma<0><<<dim3(18, TT, 2), 128, GSMEM>>>(
        wofh, xTp /*unused explicit*/, xTp, offp, R5, OFFC,
        PP, (long long)OFFC * PP, nullptr);

    sample_k<<<dim3(TT, 72, 4), 256>>>(xTp, offp, Bsp);

    cudaStreamWaitEvent(0, g_e2, 0);
    gemm_mma<1><<<dim3(18, TT, 2), 128, GSMEM>>>(
        wfh, Bsp, xTp, out, RF, 256, (long long)TT * PP, PP, b_temp);
}